// round 2
// baseline (speedup 1.0000x reference)
#include <cuda_runtime.h>
#include <math_constants.h>

#define NQ 6
#define DM 128
#define SEQ 2048
#define CHUNK 16
#define BATCH 128
#define NCHUNK (SEQ / CHUNK)      // 128
#define NROWS (BATCH * NCHUNK)    // 16384

// Scratch (device globals; no allocation allowed)
__device__ float g_params[NROWS * 128];  // per row: fp[60], mp[60], ang[6], pad[2]
__device__ float g_cf[NROWS * 128];      // per row: chunk feature (DM)

// ===========================================================================
// Kernel 1: conv1d + LN + chunk attention + pp/ep projections
// one block (128 threads) per chunk-row
// ===========================================================================
__global__ __launch_bounds__(128) void k1(
    const float* __restrict__ x, const float* __restrict__ conv_w, const float* __restrict__ conv_b,
    const float* __restrict__ ln1_g, const float* __restrict__ ln1_b,
    const float* __restrict__ ca1_w, const float* __restrict__ ca1_b,
    const float* __restrict__ ca2_w, const float* __restrict__ ca2_b,
    const float* __restrict__ pp_w, const float* __restrict__ pp_b,
    const float* __restrict__ ep_w, const float* __restrict__ ep_b)
{
    int r = blockIdx.x;
    int b = r >> 7;
    int ch = r & 127;
    int s0 = ch * CHUNK;
    int t = threadIdx.x;
    int lane = t & 31, warp = t >> 5;

    __shared__ float sx[4][CHUNK + 2];
    __shared__ float h_s[CHUNK * 129];       // stride 129: conflict-free column reads
    __shared__ float wred[CHUNK][4][2];
    __shared__ float mv_s[CHUNK], rv_s[CHUNK];
    __shared__ float sc_s[CHUNK];
    __shared__ float wgt_s[CHUNK];
    __shared__ float summ_s[DM];

    // load x slice with halo (4 channels x 18)
    if (t < 72) {
        int c = t / 18, k = t % 18;
        int s = s0 - 1 + k;
        float v = 0.f;
        if (s >= 0 && s < SEQ) v = x[(b * 4 + c) * SEQ + s];
        sx[c][k] = v;
    }
    __syncthreads();

    // conv: thread t = output channel d
    float w0[12];
#pragma unroll
    for (int i = 0; i < 12; i++) w0[i] = conv_w[t * 12 + i];
    float bias = conv_b[t];
    float h[CHUNK];
#pragma unroll
    for (int p = 0; p < CHUNK; p++) {
        float a = bias;
#pragma unroll
        for (int c = 0; c < 4; c++)
#pragma unroll
            for (int k = 0; k < 3; k++)
                a += sx[c][p + k] * w0[c * 3 + k];
        h[p] = a;
    }

    // LayerNorm over DM for each of 16 positions
#pragma unroll
    for (int p = 0; p < CHUNK; p++) {
        float v = h[p], vv = v * v;
#pragma unroll
        for (int o = 16; o; o >>= 1) {
            v += __shfl_xor_sync(0xffffffffu, v, o);
            vv += __shfl_xor_sync(0xffffffffu, vv, o);
        }
        if (lane == 0) { wred[p][warp][0] = v; wred[p][warp][1] = vv; }
    }
    __syncthreads();
    if (t < CHUNK) {
        float s = 0.f, ss = 0.f;
#pragma unroll
        for (int w = 0; w < 4; w++) { s += wred[t][w][0]; ss += wred[t][w][1]; }
        float m = s * (1.f / DM);
        float var = ss * (1.f / DM) - m * m;
        mv_s[t] = m; rv_s[t] = rsqrtf(var + 1e-5f);
    }
    __syncthreads();
    {
        float g = ln1_g[t], bb = ln1_b[t];
#pragma unroll
        for (int p = 0; p < CHUNK; p++) {
            float hn = (h[p] - mv_s[p]) * rv_s[p] * g + bb;
            h[p] = hn;
            h_s[p * 129 + t] = hn;
        }
    }
    __syncthreads();

    // chunk attention scores: thread -> (p = t>>3, 4 cols jb..jb+3)
    {
        int p = t >> 3;
        int jb = (t & 7) * 4;
        float a0 = 0.f, a1 = 0.f, a2 = 0.f, a3 = 0.f;
        const float4* w4 = reinterpret_cast<const float4*>(ca1_w);
        for (int d = 0; d < DM; d++) {
            float hv = h_s[p * 129 + d];
            float4 w = __ldg(&w4[d * 8 + (jb >> 2)]);
            a0 += hv * w.x; a1 += hv * w.y; a2 += hv * w.z; a3 += hv * w.w;
        }
        float part = tanhf(a0 + ca1_b[jb])     * ca2_w[jb]
                   + tanhf(a1 + ca1_b[jb + 1]) * ca2_w[jb + 1]
                   + tanhf(a2 + ca1_b[jb + 2]) * ca2_w[jb + 2]
                   + tanhf(a3 + ca1_b[jb + 3]) * ca2_w[jb + 3];
#pragma unroll
        for (int o = 4; o; o >>= 1) part += __shfl_down_sync(0xffffffffu, part, o, 8);
        if ((t & 7) == 0) sc_s[p] = part + ca2_b[0];
    }
    __syncthreads();

    // softmax over 16 positions (warp 0)
    if (t < 32) {
        float v = (lane < CHUNK) ? sc_s[lane] : -CUDART_INF_F;
        float m = v;
#pragma unroll
        for (int o = 8; o; o >>= 1) m = fmaxf(m, __shfl_xor_sync(0xffffffffu, m, o, 16));
        float e = (lane < CHUNK) ? expf(v - m) : 0.f;
        float sm = e;
#pragma unroll
        for (int o = 8; o; o >>= 1) sm += __shfl_xor_sync(0xffffffffu, sm, o, 16);
        if (lane < CHUNK) wgt_s[lane] = e / sm;
    }
    __syncthreads();

    // weighted sum -> summ (per-thread: own channel)
    {
        float smv = 0.f;
#pragma unroll
        for (int p = 0; p < CHUNK; p++) smv += wgt_s[p] * h[p];
        summ_s[t] = smv;
    }
    __syncthreads();

    // projections: pp (120) and ep->ang (6)
    if (t < 120) {
        float a = pp_b[t];
        for (int d = 0; d < DM; d++) a += summ_s[d] * __ldg(&pp_w[d * 120 + t]);
        g_params[r * 128 + t] = a;
    } else if (t < 126) {
        int j = t - 120;
        float a = ep_b[j];
        for (int d = 0; d < DM; d++) a += summ_s[d] * __ldg(&ep_w[d * 6 + j]);
        g_params[r * 128 + 120 + j] = tanhf(a) * 3.14159265358979323846f;
    }
}

// ===========================================================================
// Kernel 2: quantum circuit (warp per row) + op projection + LN + SiLU
// state: 64 complex amps; lane bits 4..0 = qubits 0..4, register idx = qubit 5
// ===========================================================================
__device__ __forceinline__ void gate_rx(int q, float t, int lane,
    float& ar0, float& ai0, float& ar1, float& ai1)
{
    float s, c; __sincosf(0.5f * t, &s, &c);
    if (q == 5) {
        float nr0 = c * ar0 + s * ai1, ni0 = c * ai0 - s * ar1;
        float nr1 = c * ar1 + s * ai0, ni1 = c * ai1 - s * ar0;
        ar0 = nr0; ai0 = ni0; ar1 = nr1; ai1 = ni1;
    } else {
        int m = 1 << (4 - q);
        float br0 = __shfl_xor_sync(0xffffffffu, ar0, m), bi0 = __shfl_xor_sync(0xffffffffu, ai0, m);
        float br1 = __shfl_xor_sync(0xffffffffu, ar1, m), bi1 = __shfl_xor_sync(0xffffffffu, ai1, m);
        ar0 = c * ar0 + s * bi0; ai0 = c * ai0 - s * br0;
        ar1 = c * ar1 + s * bi1; ai1 = c * ai1 - s * br1;
    }
}

__device__ __forceinline__ void gate_ry(int q, float t, int lane,
    float& ar0, float& ai0, float& ar1, float& ai1)
{
    float s, c; __sincosf(0.5f * t, &s, &c);
    if (q == 5) {
        float nr0 = c * ar0 - s * ar1, ni0 = c * ai0 - s * ai1;
        float nr1 = s * ar0 + c * ar1, ni1 = s * ai0 + c * ai1;
        ar0 = nr0; ai0 = ni0; ar1 = nr1; ai1 = ni1;
    } else {
        int m = 1 << (4 - q);
        float br0 = __shfl_xor_sync(0xffffffffu, ar0, m), bi0 = __shfl_xor_sync(0xffffffffu, ai0, m);
        float br1 = __shfl_xor_sync(0xffffffffu, ar1, m), bi1 = __shfl_xor_sync(0xffffffffu, ai1, m);
        float sg = ((lane >> (4 - q)) & 1) ? s : -s;
        ar0 = c * ar0 + sg * br0; ai0 = c * ai0 + sg * bi0;
        ar1 = c * ar1 + sg * br1; ai1 = c * ai1 + sg * bi1;
    }
}

__device__ __forceinline__ void gate_rz(int q, float t, int lane,
    float& ar0, float& ai0, float& ar1, float& ai1)
{
    float s, c; __sincosf(0.5f * t, &s, &c);
    if (q == 5) {
        float nr0 = c * ar0 + s * ai0, ni0 = c * ai0 - s * ar0;  // x(c - i s)
        float nr1 = c * ar1 - s * ai1, ni1 = c * ai1 + s * ar1;  // x(c + i s)
        ar0 = nr0; ai0 = ni0; ar1 = nr1; ai1 = ni1;
    } else {
        float sg = ((lane >> (4 - q)) & 1) ? s : -s;
        float nr0 = c * ar0 - sg * ai0, ni0 = c * ai0 + sg * ar0;
        float nr1 = c * ar1 - sg * ai1, ni1 = c * ai1 + sg * ar1;
        ar0 = nr0; ai0 = ni0; ar1 = nr1; ai1 = ni1;
    }
}

__device__ __forceinline__ void gate_crx(int cq, int tq, float t, int lane,
    float& ar0, float& ai0, float& ar1, float& ai1)
{
    float s, c; __sincosf(0.5f * t, &s, &c);
    if (cq == 5) {
        // control = register index: only reg1 participates; target tq<5
        int m = 1 << (4 - tq);
        float br1 = __shfl_xor_sync(0xffffffffu, ar1, m), bi1 = __shfl_xor_sync(0xffffffffu, ai1, m);
        ar1 = c * ar1 + s * bi1; ai1 = c * ai1 - s * br1;
    } else if (tq == 5) {
        if ((lane >> (4 - cq)) & 1) {
            float nr0 = c * ar0 + s * ai1, ni0 = c * ai0 - s * ar1;
            float nr1 = c * ar1 + s * ai0, ni1 = c * ai1 - s * ar0;
            ar0 = nr0; ai0 = ni0; ar1 = nr1; ai1 = ni1;
        }
    } else {
        int m = 1 << (4 - tq);
        float br0 = __shfl_xor_sync(0xffffffffu, ar0, m), bi0 = __shfl_xor_sync(0xffffffffu, ai0, m);
        float br1 = __shfl_xor_sync(0xffffffffu, ar1, m), bi1 = __shfl_xor_sync(0xffffffffu, ai1, m);
        if ((lane >> (4 - cq)) & 1) {
            ar0 = c * ar0 + s * bi0; ai0 = c * ai0 - s * br0;
            ar1 = c * ar1 + s * bi1; ai1 = c * ai1 - s * br1;
        }
    }
}

__device__ __forceinline__ void ansatz(const float* __restrict__ p, int lane,
    float& ar0, float& ai0, float& ar1, float& ai1)
{
#pragma unroll
    for (int i = 0; i < NQ; i++) {
        gate_rx(i, p[3 * i],     lane, ar0, ai0, ar1, ai1);
        gate_ry(i, p[3 * i + 1], lane, ar0, ai0, ar1, ai1);
        gate_rz(i, p[3 * i + 2], lane, ar0, ai0, ar1, ai1);
    }
#pragma unroll
    for (int i = 0; i < NQ; i++)
        gate_crx(i, (i + 1) % NQ, p[18 + i], lane, ar0, ai0, ar1, ai1);
#pragma unroll
    for (int i = NQ - 1; i >= 0; i--)
        gate_crx(i, (i + NQ - 1) % NQ, p[24 + (NQ - 1 - i)], lane, ar0, ai0, ar1, ai1);
}

__global__ __launch_bounds__(256) void k2(
    const float* __restrict__ op_w, const float* __restrict__ op_b,
    const float* __restrict__ ln2_g, const float* __restrict__ ln2_b)
{
    int w = threadIdx.x >> 5;
    int lane = threadIdx.x & 31;
    int r = blockIdx.x * 8 + w;

    __shared__ float s_par[8][128];
#pragma unroll
    for (int j = 0; j < 4; j++)
        s_par[w][lane + 32 * j] = g_params[r * 128 + lane + 32 * j];
    __syncwarp();
    const float* par = s_par[w];
    const float* fp = par;
    const float* mp = par + 60;
    const float* ang = par + 120;

    // initial product state after per-qubit RY on |0>
    float ar0, ai0 = 0.f, ar1, ai1 = 0.f;
    {
        float a0 = 1.f, a1 = 1.f;
#pragma unroll
        for (int i = 0; i < 5; i++) {
            float s, c; __sincosf(0.5f * ang[i], &s, &c);
            float f = ((lane >> (4 - i)) & 1) ? s : c;
            a0 *= f; a1 *= f;
        }
        float s, c; __sincosf(0.5f * ang[5], &s, &c);
        ar0 = a0 * c; ar1 = a1 * s;
    }

    ansatz(fp,      lane, ar0, ai0, ar1, ai1);
    ansatz(fp + 30, lane, ar0, ai0, ar1, ai1);
    ansatz(mp,      lane, ar0, ai0, ar1, ai1);
    ansatz(mp + 30, lane, ar0, ai0, ar1, ai1);

    // measurements: X, Y, Z per qubit
    float qv[18];
#pragma unroll
    for (int i = 0; i < NQ; i++) {
        float cr, ci, z;
        float n0 = ar0 * ar0 + ai0 * ai0;
        float n1 = ar1 * ar1 + ai1 * ai1;
        if (i == 5) {
            cr = ar0 * ar1 + ai0 * ai1;
            ci = ar0 * ai1 - ai0 * ar1;
            z  = n0 - n1;
        } else {
            int m = 1 << (4 - i);
            float br0 = __shfl_xor_sync(0xffffffffu, ar0, m), bi0 = __shfl_xor_sync(0xffffffffu, ai0, m);
            float br1 = __shfl_xor_sync(0xffffffffu, ar1, m), bi1 = __shfl_xor_sync(0xffffffffu, ai1, m);
            if (((lane >> (4 - i)) & 1) == 0) {
                cr = ar0 * br0 + ai0 * bi0 + ar1 * br1 + ai1 * bi1;
                ci = ar0 * bi0 - ai0 * br0 + ar1 * bi1 - ai1 * br1;
                z  = n0 + n1;
            } else {
                cr = 0.f; ci = 0.f; z = -(n0 + n1);
            }
        }
#pragma unroll
        for (int o = 16; o; o >>= 1) {
            cr += __shfl_xor_sync(0xffffffffu, cr, o);
            ci += __shfl_xor_sync(0xffffffffu, ci, o);
            z  += __shfl_xor_sync(0xffffffffu, z, o);
        }
        qv[i] = 2.f * cr; qv[6 + i] = 2.f * ci; qv[12 + i] = z;
    }

    // op projection (18 -> 128) + LN + SiLU, 4 channels per lane
    float acc[4];
#pragma unroll
    for (int j = 0; j < 4; j++) {
        int d = lane + 32 * j;
        float a = op_b[d];
#pragma unroll
        for (int k = 0; k < 18; k++) a += qv[k] * __ldg(&op_w[k * 128 + d]);
        acc[j] = a;
    }
    float sum = acc[0] + acc[1] + acc[2] + acc[3];
#pragma unroll
    for (int o = 16; o; o >>= 1) sum += __shfl_xor_sync(0xffffffffu, sum, o);
    float mean = sum * (1.f / 128.f);
    float vs = 0.f;
#pragma unroll
    for (int j = 0; j < 4; j++) { float d0 = acc[j] - mean; vs += d0 * d0; }
#pragma unroll
    for (int o = 16; o; o >>= 1) vs += __shfl_xor_sync(0xffffffffu, vs, o);
    float rstd = rsqrtf(vs * (1.f / 128.f) + 1e-5f);
#pragma unroll
    for (int j = 0; j < 4; j++) {
        int d = lane + 32 * j;
        float xv = (acc[j] - mean) * rstd * ln2_g[d] + ln2_b[d];
        g_cf[r * 128 + d] = xv / (1.f + expf(-xv));
    }
}

// ===========================================================================
// Kernel 3: sequence attention + classifier (one block per batch row)
// ===========================================================================
__global__ __launch_bounds__(128) void k3(
    const float* __restrict__ sa1_w, const float* __restrict__ sa1_b,
    const float* __restrict__ sa2_w, const float* __restrict__ sa2_b,
    const float* __restrict__ cl1_w, const float* __restrict__ cl1_b,
    const float* __restrict__ cl2_w, const float* __restrict__ cl2_b,
    float* __restrict__ out)
{
    int b = blockIdx.x;
    int t = threadIdx.x, lane = t & 31, w = t >> 5;
    const float* cf = g_cf + (size_t)b * NCHUNK * DM;

    __shared__ float ss_s[NCHUNK];
    __shared__ float red[4];
    __shared__ float sw_s[NCHUNK];
    __shared__ float rep_s[DM];
    __shared__ float u_s[64];

    // scores: warp w handles chunks [32w, 32w+32); lane = hidden col j
    {
        float b1 = sa1_b[lane];
        float w2 = sa2_w[lane];
        for (int n = 32 * w; n < 32 * w + 32; n++) {
            float a = b1;
            const float* row = cf + n * DM;
            for (int d = 0; d < DM; d++) a += __ldg(&row[d]) * __ldg(&sa1_w[d * 32 + lane]);
            float v = tanhf(a) * w2;
#pragma unroll
            for (int o = 16; o; o >>= 1) v += __shfl_xor_sync(0xffffffffu, v, o);
            if (lane == 0) ss_s[n] = v + sa2_b[0];
        }
    }
    __syncthreads();

    // softmax over 128 chunks
    float v = ss_s[t];
    float m = v;
#pragma unroll
    for (int o = 16; o; o >>= 1) m = fmaxf(m, __shfl_xor_sync(0xffffffffu, m, o));
    if (lane == 0) red[w] = m;
    __syncthreads();
    m = fmaxf(fmaxf(red[0], red[1]), fmaxf(red[2], red[3]));
    float e = expf(v - m);
    float sl = e;
#pragma unroll
    for (int o = 16; o; o >>= 1) sl += __shfl_xor_sync(0xffffffffu, sl, o);
    __syncthreads();
    if (lane == 0) red[w] = sl;
    __syncthreads();
    float tot = red[0] + red[1] + red[2] + red[3];
    sw_s[t] = e / tot;
    __syncthreads();

    // rep[d] = sum_n sw[n] * cf[n][d]
    {
        float acc = 0.f;
        for (int n = 0; n < NCHUNK; n++) acc += sw_s[n] * cf[n * DM + t];
        rep_s[t] = acc;
    }
    __syncthreads();

    if (t < 64) {
        float a = cl1_b[t];
        for (int d = 0; d < DM; d++) a += rep_s[d] * __ldg(&cl1_w[d * 64 + t]);
        u_s[t] = a / (1.f + expf(-a));
    }
    __syncthreads();
    if (t < 2) {
        float a = cl2_b[t];
        for (int j = 0; j < 64; j++) a += u_s[j] * __ldg(&cl2_w[j * 2 + t]);
        out[b * 2 + t] = a;
    }
}

// ===========================================================================
extern "C" void kernel_launch(void* const* d_in, const int* in_sizes, int n_in,
                              void* d_out, int out_size)
{
    const float* x      = (const float*)d_in[0];
    const float* conv_w = (const float*)d_in[1];
    const float* conv_b = (const float*)d_in[2];
    const float* ln1_g  = (const float*)d_in[3];
    const float* ln1_b  = (const float*)d_in[4];
    const float* ca1_w  = (const float*)d_in[5];
    const float* ca1_b  = (const float*)d_in[6];
    const float* ca2_w  = (const float*)d_in[7];
    const float* ca2_b  = (const float*)d_in[8];
    const float* pp_w   = (const float*)d_in[9];
    const float* pp_b   = (const float*)d_in[10];
    const float* ep_w   = (const float*)d_in[11];
    const float* ep_b   = (const float*)d_in[12];
    const float* op_w   = (const float*)d_in[13];
    const float* op_b   = (const float*)d_in[14];
    const float* ln2_g  = (const float*)d_in[15];
    const float* ln2_b  = (const float*)d_in[16];
    const float* sa1_w  = (const float*)d_in[17];
    const float* sa1_b  = (const float*)d_in[18];
    const float* sa2_w  = (const float*)d_in[19];
    const float* sa2_b  = (const float*)d_in[20];
    const float* cl1_w  = (const float*)d_in[21];
    const float* cl1_b  = (const float*)d_in[22];
    const float* cl2_w  = (const float*)d_in[23];
    const float* cl2_b  = (const float*)d_in[24];
    float* out = (float*)d_out;

    k1<<<NROWS, 128>>>(x, conv_w, conv_b, ln1_g, ln1_b, ca1_w, ca1_b, ca2_w, ca2_b,
                       pp_w, pp_b, ep_w, ep_b);
    k2<<<NROWS / 8, 256>>>(op_w, op_b, ln2_g, ln2_b);
    k3<<<BATCH, 128>>>(sa1_w, sa1_b, sa2_w, sa2_b, cl1_w, cl1_b, cl2_w, cl2_b, out);
}

// round 3
// speedup vs baseline: 1.2754x; 1.2754x over previous
#include <cuda_runtime.h>
#include <math_constants.h>

#define NQ 6
#define DM 128
#define SEQ 2048
#define CHUNK 16
#define BATCH 128
#define NCHUNK (SEQ / CHUNK)      // 128
#define NROWS (BATCH * NCHUNK)    // 16384

// Scratch (device globals; no allocation allowed)
__device__ float g_params[NROWS * 128];  // per row: fp[60], mp[60], ang[6], pad[2]
__device__ float g_summ[NROWS * 128];    // per row: summ (DM)
__device__ float g_cf[NROWS * 128];      // per row: chunk feature (DM)

__device__ __forceinline__ float tanh_fast(float x) {
    float y; asm("tanh.approx.f32 %0, %1;" : "=f"(y) : "f"(x)); return y;
}

// ===========================================================================
// Kernel 1: conv1d + LN + chunk attention + ep projection
// one block = 8 chunks (128 seq positions) of one batch row; 256 threads
// h stored d-major: ht[d*130 + p]
// ===========================================================================
struct K1Smem {
    float sx[4][132];
    float ht[128 * 130];
    float w1[128 * 32];
    float cw[128 * 13];
    float lng[128], lnb[128];
    float b1[32], w2[32];
    float scp[4 * 128];
    float sc[128];
    float wgt[128];
    float mv[128], rv[128];
    float summ[8 * 128];
    float epw[768];
    float epb[8];
};

__global__ __launch_bounds__(256) void k1(
    const float* __restrict__ x, const float* __restrict__ conv_w, const float* __restrict__ conv_b,
    const float* __restrict__ ln1_g, const float* __restrict__ ln1_b,
    const float* __restrict__ ca1_w, const float* __restrict__ ca1_b,
    const float* __restrict__ ca2_w, const float* __restrict__ ca2_b,
    const float* __restrict__ ep_w, const float* __restrict__ ep_b)
{
    extern __shared__ char smem_raw[];
    K1Smem& S = *reinterpret_cast<K1Smem*>(smem_raw);

    const int bid = blockIdx.x;
    const int b = bid >> 4;          // batch
    const int g = bid & 15;          // chunk-group (8 chunks)
    const int s_base = g * 128;
    const int t = threadIdx.x;

    // ---- stage weights + input slice ----
    for (int i = t; i < 4096; i += 256) S.w1[i] = ca1_w[i];
    for (int i = t; i < 1536; i += 256) S.cw[(i / 12) * 13 + (i % 12)] = conv_w[i];
    if (t < 128) { S.lng[t] = ln1_g[t]; S.lnb[t] = ln1_b[t]; }
    if (t < 32) { S.b1[t] = ca1_b[t]; S.w2[t] = ca2_w[t]; }
    for (int i = t; i < 768; i += 256) S.epw[i] = ep_w[i];
    if (t < 6) S.epb[t] = ep_b[t];
    for (int i = t; i < 4 * 130; i += 256) {
        int c = i / 130, k = i % 130;
        int s = s_base - 1 + k;
        float v = 0.f;
        if (s >= 0 && s < SEQ) v = x[(b * 4 + c) * SEQ + s];
        S.sx[c][k] = v;
    }
    __syncthreads();

    // ---- conv: thread = (channel d, position half); 64 contiguous positions ----
    const int d = t & 127;
    const int half = t >> 7;
    {
        const int p0c = half * 64;
        float w0[12];
#pragma unroll
        for (int k = 0; k < 12; k++) w0[k] = S.cw[d * 13 + k];
        float bias = conv_b[d];
        float x0[4], x1[4];
#pragma unroll
        for (int c = 0; c < 4; c++) { x0[c] = S.sx[c][p0c]; x1[c] = S.sx[c][p0c + 1]; }
#pragma unroll 4
        for (int p = p0c; p < p0c + 64; p++) {
            float a = bias;
#pragma unroll
            for (int c = 0; c < 4; c++) {
                float x2 = S.sx[c][p + 2];
                a = fmaf(x0[c], w0[c * 3 + 0], a);
                a = fmaf(x1[c], w0[c * 3 + 1], a);
                a = fmaf(x2,    w0[c * 3 + 2], a);
                x0[c] = x1[c]; x1[c] = x2;
            }
            S.ht[d * 130 + p] = a;
        }
    }
    __syncthreads();

    // ---- LayerNorm stats: thread = position ----
    if (t < 128) {
        float s = 0.f, ss = 0.f;
        for (int dd = 0; dd < 128; dd++) {
            float v = S.ht[dd * 130 + t];
            s += v; ss = fmaf(v, v, ss);
        }
        float m = s * (1.f / 128.f);
        float var = ss * (1.f / 128.f) - m * m;
        S.mv[t] = m; S.rv[t] = rsqrtf(var + 1e-5f);
    }
    __syncthreads();
    // ---- normalize in place ----
    for (int i = t; i < 16384; i += 256) {
        int dd = i & 127, p = i >> 7;
        float v = S.ht[dd * 130 + p];
        S.ht[dd * 130 + p] = (v - S.mv[p]) * S.rv[p] * S.lng[dd] + S.lnb[dd];
    }
    __syncthreads();

    // ---- scores: thread = (pos-pair pp, col-group jq of 8) ----
    {
        const int pp = t & 63;
        const int p0 = 2 * pp;
        const int jq = t >> 6;
        const int j0 = 8 * jq;
        float acc[16];
#pragma unroll
        for (int i = 0; i < 16; i++) acc[i] = 0.f;
        for (int dd = 0; dd < 128; dd++) {
            float2 h2 = *reinterpret_cast<const float2*>(&S.ht[dd * 130 + p0]);
            float4 wa = *reinterpret_cast<const float4*>(&S.w1[dd * 32 + j0]);
            float4 wb = *reinterpret_cast<const float4*>(&S.w1[dd * 32 + j0 + 4]);
            acc[0] = fmaf(h2.x, wa.x, acc[0]);  acc[1] = fmaf(h2.x, wa.y, acc[1]);
            acc[2] = fmaf(h2.x, wa.z, acc[2]);  acc[3] = fmaf(h2.x, wa.w, acc[3]);
            acc[4] = fmaf(h2.x, wb.x, acc[4]);  acc[5] = fmaf(h2.x, wb.y, acc[5]);
            acc[6] = fmaf(h2.x, wb.z, acc[6]);  acc[7] = fmaf(h2.x, wb.w, acc[7]);
            acc[8]  = fmaf(h2.y, wa.x, acc[8]);  acc[9]  = fmaf(h2.y, wa.y, acc[9]);
            acc[10] = fmaf(h2.y, wa.z, acc[10]); acc[11] = fmaf(h2.y, wa.w, acc[11]);
            acc[12] = fmaf(h2.y, wb.x, acc[12]); acc[13] = fmaf(h2.y, wb.y, acc[13]);
            acc[14] = fmaf(h2.y, wb.z, acc[14]); acc[15] = fmaf(h2.y, wb.w, acc[15]);
        }
#pragma unroll
        for (int r = 0; r < 2; r++) {
            float sp = 0.f;
#pragma unroll
            for (int k = 0; k < 8; k++)
                sp = fmaf(tanh_fast(acc[r * 8 + k] + S.b1[j0 + k]), S.w2[j0 + k], sp);
            S.scp[jq * 128 + p0 + r] = sp;
        }
    }
    __syncthreads();

    // ---- combine + softmax per chunk (width-16 shuffles) ----
    if (t < 128) {
        float v = S.scp[t] + S.scp[128 + t] + S.scp[256 + t] + S.scp[384 + t] + ca2_b[0];
        float m = v;
#pragma unroll
        for (int o = 8; o; o >>= 1) m = fmaxf(m, __shfl_xor_sync(0xffffffffu, m, o, 16));
        float e = __expf(v - m);
        float sm = e;
#pragma unroll
        for (int o = 8; o; o >>= 1) sm += __shfl_xor_sync(0xffffffffu, sm, o, 16);
        S.wgt[t] = e / sm;
    }
    __syncthreads();

    // ---- weighted sums (8 chunks) ----
    {
        for (int c = 4 * half; c < 4 * half + 4; c++) {
            float a = 0.f;
#pragma unroll
            for (int p = 0; p < 16; p++)
                a = fmaf(S.wgt[c * 16 + p], S.ht[d * 130 + c * 16 + p], a);
            S.summ[c * 128 + d] = a;
            g_summ[(b * 128 + g * 8 + c) * 128 + d] = a;
        }
    }
    __syncthreads();

    // ---- ep projection -> angles (precise tanh: feeds quantum circuit) ----
    if (t < 48) {
        int r = t / 6, j = t % 6;
        float a = S.epb[j];
        for (int dd = 0; dd < 128; dd++)
            a = fmaf(S.summ[r * 128 + dd], S.epw[dd * 6 + j], a);
        g_params[(b * 128 + g * 8 + r) * 128 + 120 + j] =
            tanhf(a) * 3.14159265358979323846f;
    }
}

// ===========================================================================
// Kernel k_pp: pp projection GEMM  (16384 x 128) @ (128 x 120)
// 64 rows/block, 256 blocks; 4x8 register tile per thread
// ===========================================================================
struct KPSmem {
    float w[128 * 128];   // cols 0..119 valid, 120..127 zero
    float s[64 * 129];
};

__global__ __launch_bounds__(256) void k_pp(
    const float* __restrict__ pp_w, const float* __restrict__ pp_b)
{
    extern __shared__ char smem_raw[];
    KPSmem& S = *reinterpret_cast<KPSmem*>(smem_raw);
    const int t = threadIdx.x;
    const int r0 = blockIdx.x * 64;

    for (int i = t; i < 128 * 128; i += 256) S.w[i] = 0.f;
    __syncthreads();
    for (int i = t; i < 128 * 120; i += 256) {
        int dd = i / 120, j = i % 120;
        S.w[dd * 128 + j] = pp_w[i];
    }
    for (int i = t; i < 64 * 128; i += 256) {
        int r = i >> 7, c = i & 127;
        S.s[r * 129 + c] = g_summ[(r0 + r) * 128 + c];
    }
    __syncthreads();

    const int tx = t & 15;         // col group of 8
    const int ty = t >> 4;         // row group of 4
    float acc[4][8];
#pragma unroll
    for (int i = 0; i < 4; i++)
#pragma unroll
        for (int k = 0; k < 8; k++) acc[i][k] = 0.f;

    for (int dd = 0; dd < 128; dd++) {
        float4 wa = *reinterpret_cast<const float4*>(&S.w[dd * 128 + 8 * tx]);
        float4 wb = *reinterpret_cast<const float4*>(&S.w[dd * 128 + 8 * tx + 4]);
        float sv[4];
#pragma unroll
        for (int i = 0; i < 4; i++) sv[i] = S.s[(4 * ty + i) * 129 + dd];
#pragma unroll
        for (int i = 0; i < 4; i++) {
            acc[i][0] = fmaf(sv[i], wa.x, acc[i][0]);
            acc[i][1] = fmaf(sv[i], wa.y, acc[i][1]);
            acc[i][2] = fmaf(sv[i], wa.z, acc[i][2]);
            acc[i][3] = fmaf(sv[i], wa.w, acc[i][3]);
            acc[i][4] = fmaf(sv[i], wb.x, acc[i][4]);
            acc[i][5] = fmaf(sv[i], wb.y, acc[i][5]);
            acc[i][6] = fmaf(sv[i], wb.z, acc[i][6]);
            acc[i][7] = fmaf(sv[i], wb.w, acc[i][7]);
        }
    }
#pragma unroll
    for (int i = 0; i < 4; i++) {
        int gr = r0 + 4 * ty + i;
#pragma unroll
        for (int k = 0; k < 8; k++) {
            int j = 8 * tx + k;
            if (j < 120) g_params[gr * 128 + j] = acc[i][k] + pp_b[j];
        }
    }
}

// ===========================================================================
// Kernel 2: quantum circuit (warp per row) + op projection + LN + SiLU
// state: 64 complex amps; lane bits 4..0 = qubits 0..4, register idx = qubit 5
// ===========================================================================

// fused RX(a)->RY(b)->RZ(g) as one SU(2) butterfly U = [[P, Q],[-conj(Q), conj(P)]]
__device__ __forceinline__ void fused_rxyz(int q, float a, float b_, float g, int lane,
    float& ar0, float& ai0, float& ar1, float& ai1)
{
    float sa, ca; __sincosf(0.5f * a,  &sa, &ca);
    float sb, cb; __sincosf(0.5f * b_, &sb, &cb);
    float sg, cg; __sincosf(0.5f * g,  &sg, &cg);
    float ur = cb * ca, ui = sb * sa;
    float wr = sb * ca, wi = -cb * sa;
    float Pr = cg * ur + sg * ui, Pi = cg * ui - sg * ur;
    float Qr = sg * wi - cg * wr;   // = -(cg*wr - sg*wi)
    float Qi = cg * wi + sg * wr;

    if (q == 5) {
        float n0r =  Pr * ar0 - Pi * ai0 + Qr * ar1 - Qi * ai1;
        float n0i =  Pr * ai0 + Pi * ar0 + Qr * ai1 + Qi * ar1;
        float n1r = -Qr * ar0 - Qi * ai0 + Pr * ar1 + Pi * ai1;
        float n1i = -Qr * ai0 + Qi * ar0 + Pr * ai1 - Pi * ar1;
        ar0 = n0r; ai0 = n0i; ar1 = n1r; ai1 = n1i;
    } else {
        int m = 1 << (4 - q);
        float br0 = __shfl_xor_sync(0xffffffffu, ar0, m), bi0 = __shfl_xor_sync(0xffffffffu, ai0, m);
        float br1 = __shfl_xor_sync(0xffffffffu, ar1, m), bi1 = __shfl_xor_sync(0xffffffffu, ai1, m);
        int bit = (lane >> (4 - q)) & 1;
        float lPi = bit ? -Pi : Pi;
        float lQr = bit ? -Qr : Qr;
        float n0r = Pr * ar0 - lPi * ai0 + lQr * br0 - Qi * bi0;
        float n0i = Pr * ai0 + lPi * ar0 + lQr * bi0 + Qi * br0;
        float n1r = Pr * ar1 - lPi * ai1 + lQr * br1 - Qi * bi1;
        float n1i = Pr * ai1 + lPi * ar1 + lQr * bi1 + Qi * br1;
        ar0 = n0r; ai0 = n0i; ar1 = n1r; ai1 = n1i;
    }
}

__device__ __forceinline__ void gate_crx(int cq, int tq, float t, int lane,
    float& ar0, float& ai0, float& ar1, float& ai1)
{
    float s, c; __sincosf(0.5f * t, &s, &c);
    if (cq == 5) {
        int m = 1 << (4 - tq);
        float br1 = __shfl_xor_sync(0xffffffffu, ar1, m), bi1 = __shfl_xor_sync(0xffffffffu, ai1, m);
        ar1 = c * ar1 + s * bi1; ai1 = c * ai1 - s * br1;
    } else if (tq == 5) {
        if ((lane >> (4 - cq)) & 1) {
            float nr0 = c * ar0 + s * ai1, ni0 = c * ai0 - s * ar1;
            float nr1 = c * ar1 + s * ai0, ni1 = c * ai1 - s * ar0;
            ar0 = nr0; ai0 = ni0; ar1 = nr1; ai1 = ni1;
        }
    } else {
        int m = 1 << (4 - tq);
        float br0 = __shfl_xor_sync(0xffffffffu, ar0, m), bi0 = __shfl_xor_sync(0xffffffffu, ai0, m);
        float br1 = __shfl_xor_sync(0xffffffffu, ar1, m), bi1 = __shfl_xor_sync(0xffffffffu, ai1, m);
        if ((lane >> (4 - cq)) & 1) {
            ar0 = c * ar0 + s * bi0; ai0 = c * ai0 - s * br0;
            ar1 = c * ar1 + s * bi1; ai1 = c * ai1 - s * br1;
        }
    }
}

__device__ __forceinline__ void ansatz(const float* __restrict__ p, int lane,
    float& ar0, float& ai0, float& ar1, float& ai1)
{
#pragma unroll
    for (int i = 0; i < NQ; i++)
        fused_rxyz(i, p[3 * i], p[3 * i + 1], p[3 * i + 2], lane, ar0, ai0, ar1, ai1);
#pragma unroll
    for (int i = 0; i < NQ; i++)
        gate_crx(i, (i + 1) % NQ, p[18 + i], lane, ar0, ai0, ar1, ai1);
#pragma unroll
    for (int i = NQ - 1; i >= 0; i--)
        gate_crx(i, (i + NQ - 1) % NQ, p[24 + (NQ - 1 - i)], lane, ar0, ai0, ar1, ai1);
}

__global__ __launch_bounds__(256) void k2(
    const float* __restrict__ op_w, const float* __restrict__ op_b,
    const float* __restrict__ ln2_g, const float* __restrict__ ln2_b)
{
    int w = threadIdx.x >> 5;
    int lane = threadIdx.x & 31;
    int r = blockIdx.x * 8 + w;

    __shared__ float s_par[8][128];
#pragma unroll
    for (int j = 0; j < 4; j++)
        s_par[w][lane + 32 * j] = g_params[r * 128 + lane + 32 * j];
    __syncwarp();
    const float* par = s_par[w];
    const float* fp = par;
    const float* mp = par + 60;
    const float* ang = par + 120;

    // initial product state after per-qubit RY on |0>
    float ar0, ai0 = 0.f, ar1, ai1 = 0.f;
    {
        float a0 = 1.f, a1 = 1.f;
#pragma unroll
        for (int i = 0; i < 5; i++) {
            float s, c; __sincosf(0.5f * ang[i], &s, &c);
            float f = ((lane >> (4 - i)) & 1) ? s : c;
            a0 *= f; a1 *= f;
        }
        float s, c; __sincosf(0.5f * ang[5], &s, &c);
        ar0 = a0 * c; ar1 = a1 * s;
    }

    ansatz(fp,      lane, ar0, ai0, ar1, ai1);
    ansatz(fp + 30, lane, ar0, ai0, ar1, ai1);
    ansatz(mp,      lane, ar0, ai0, ar1, ai1);
    ansatz(mp + 30, lane, ar0, ai0, ar1, ai1);

    // measurements: X, Y, Z per qubit
    float qv[18];
#pragma unroll
    for (int i = 0; i < NQ; i++) {
        float cr, ci, z;
        float n0 = ar0 * ar0 + ai0 * ai0;
        float n1 = ar1 * ar1 + ai1 * ai1;
        if (i == 5) {
            cr = ar0 * ar1 + ai0 * ai1;
            ci = ar0 * ai1 - ai0 * ar1;
            z  = n0 - n1;
        } else {
            int m = 1 << (4 - i);
            float br0 = __shfl_xor_sync(0xffffffffu, ar0, m), bi0 = __shfl_xor_sync(0xffffffffu, ai0, m);
            float br1 = __shfl_xor_sync(0xffffffffu, ar1, m), bi1 = __shfl_xor_sync(0xffffffffu, ai1, m);
            if (((lane >> (4 - i)) & 1) == 0) {
                cr = ar0 * br0 + ai0 * bi0 + ar1 * br1 + ai1 * bi1;
                ci = ar0 * bi0 - ai0 * br0 + ar1 * bi1 - ai1 * br1;
                z  = n0 + n1;
            } else {
                cr = 0.f; ci = 0.f; z = -(n0 + n1);
            }
        }
#pragma unroll
        for (int o = 16; o; o >>= 1) {
            cr += __shfl_xor_sync(0xffffffffu, cr, o);
            ci += __shfl_xor_sync(0xffffffffu, ci, o);
            z  += __shfl_xor_sync(0xffffffffu, z, o);
        }
        qv[i] = 2.f * cr; qv[6 + i] = 2.f * ci; qv[12 + i] = z;
    }

    // op projection (18 -> 128) + LN + SiLU, 4 channels per lane
    float acc[4];
#pragma unroll
    for (int j = 0; j < 4; j++) {
        int d = lane + 32 * j;
        float a = op_b[d];
#pragma unroll
        for (int k = 0; k < 18; k++) a = fmaf(qv[k], __ldg(&op_w[k * 128 + d]), a);
        acc[j] = a;
    }
    float sum = acc[0] + acc[1] + acc[2] + acc[3];
#pragma unroll
    for (int o = 16; o; o >>= 1) sum += __shfl_xor_sync(0xffffffffu, sum, o);
    float mean = sum * (1.f / 128.f);
    float vs = 0.f;
#pragma unroll
    for (int j = 0; j < 4; j++) { float d0 = acc[j] - mean; vs = fmaf(d0, d0, vs); }
#pragma unroll
    for (int o = 16; o; o >>= 1) vs += __shfl_xor_sync(0xffffffffu, vs, o);
    float rstd = rsqrtf(vs * (1.f / 128.f) + 1e-5f);
#pragma unroll
    for (int j = 0; j < 4; j++) {
        int d = lane + 32 * j;
        float xv = (acc[j] - mean) * rstd * ln2_g[d] + ln2_b[d];
        g_cf[r * 128 + d] = xv / (1.f + __expf(-xv));
    }
}

// ===========================================================================
// Kernel 3: sequence attention + classifier (one block per batch row)
// ===========================================================================
__global__ __launch_bounds__(128) void k3(
    const float* __restrict__ sa1_w, const float* __restrict__ sa1_b,
    const float* __restrict__ sa2_w, const float* __restrict__ sa2_b,
    const float* __restrict__ cl1_w, const float* __restrict__ cl1_b,
    const float* __restrict__ cl2_w, const float* __restrict__ cl2_b,
    float* __restrict__ out)
{
    int b = blockIdx.x;
    int t = threadIdx.x, lane = t & 31, w = t >> 5;
    const float* cf = g_cf + (size_t)b * NCHUNK * DM;

    __shared__ float ss_s[NCHUNK];
    __shared__ float red[4];
    __shared__ float sw_s[NCHUNK];
    __shared__ float rep_s[DM];
    __shared__ float u_s[64];

    {
        float b1 = sa1_b[lane];
        float w2 = sa2_w[lane];
        for (int n = 32 * w; n < 32 * w + 32; n++) {
            float a = b1;
            const float* row = cf + n * DM;
            for (int d = 0; d < DM; d++) a = fmaf(__ldg(&row[d]), __ldg(&sa1_w[d * 32 + lane]), a);
            float v = tanh_fast(a) * w2;
#pragma unroll
            for (int o = 16; o; o >>= 1) v += __shfl_xor_sync(0xffffffffu, v, o);
            if (lane == 0) ss_s[n] = v + sa2_b[0];
        }
    }
    __syncthreads();

    float v = ss_s[t];
    float m = v;
#pragma unroll
    for (int o = 16; o; o >>= 1) m = fmaxf(m, __shfl_xor_sync(0xffffffffu, m, o));
    if (lane == 0) red[w] = m;
    __syncthreads();
    m = fmaxf(fmaxf(red[0], red[1]), fmaxf(red[2], red[3]));
    float e = __expf(v - m);
    float sl = e;
#pragma unroll
    for (int o = 16; o; o >>= 1) sl += __shfl_xor_sync(0xffffffffu, sl, o);
    __syncthreads();
    if (lane == 0) red[w] = sl;
    __syncthreads();
    float tot = red[0] + red[1] + red[2] + red[3];
    sw_s[t] = e / tot;
    __syncthreads();

    {
        float acc = 0.f;
        for (int n = 0; n < NCHUNK; n++) acc = fmaf(sw_s[n], cf[n * DM + t], acc);
        rep_s[t] = acc;
    }
    __syncthreads();

    if (t < 64) {
        float a = cl1_b[t];
        for (int d = 0; d < DM; d++) a = fmaf(rep_s[d], __ldg(&cl1_w[d * 64 + t]), a);
        u_s[t] = a / (1.f + __expf(-a));
    }
    __syncthreads();
    if (t < 2) {
        float a = cl2_b[t];
        for (int j = 0; j < 64; j++) a = fmaf(u_s[j], __ldg(&cl2_w[j * 2 + t]), a);
        out[b * 2 + t] = a;
    }
}

// ===========================================================================
extern "C" void kernel_launch(void* const* d_in, const int* in_sizes, int n_in,
                              void* d_out, int out_size)
{
    const float* x      = (const float*)d_in[0];
    const float* conv_w = (const float*)d_in[1];
    const float* conv_b = (const float*)d_in[2];
    const float* ln1_g  = (const float*)d_in[3];
    const float* ln1_b  = (const float*)d_in[4];
    const float* ca1_w  = (const float*)d_in[5];
    const float* ca1_b  = (const float*)d_in[6];
    const float* ca2_w  = (const float*)d_in[7];
    const float* ca2_b  = (const float*)d_in[8];
    const float* pp_w   = (const float*)d_in[9];
    const float* pp_b   = (const float*)d_in[10];
    const float* ep_w   = (const float*)d_in[11];
    const float* ep_b   = (const float*)d_in[12];
    const float* op_w   = (const float*)d_in[13];
    const float* op_b   = (const float*)d_in[14];
    const float* ln2_g  = (const float*)d_in[15];
    const float* ln2_b  = (const float*)d_in[16];
    const float* sa1_w  = (const float*)d_in[17];
    const float* sa1_b  = (const float*)d_in[18];
    const float* sa2_w  = (const float*)d_in[19];
    const float* sa2_b  = (const float*)d_in[20];
    const float* cl1_w  = (const float*)d_in[21];
    const float* cl1_b  = (const float*)d_in[22];
    const float* cl2_w  = (const float*)d_in[23];
    const float* cl2_b  = (const float*)d_in[24];
    float* out = (float*)d_out;

    cudaFuncSetAttribute(k1, cudaFuncAttributeMaxDynamicSharedMemorySize, (int)sizeof(K1Smem));
    cudaFuncSetAttribute(k_pp, cudaFuncAttributeMaxDynamicSharedMemorySize, (int)sizeof(KPSmem));

    k1<<<BATCH * 16, 256, sizeof(K1Smem)>>>(x, conv_w, conv_b, ln1_g, ln1_b,
                                            ca1_w, ca1_b, ca2_w, ca2_b, ep_w, ep_b);
    k_pp<<<NROWS / 64, 256, sizeof(KPSmem)>>>(pp_w, pp_b);
    k2<<<NROWS / 8, 256>>>(op_w, op_b, ln2_g, ln2_b);
    k3<<<BATCH, 128>>>(sa1_w, sa1_b, sa2_w, sa2_b, cl1_w, cl1_b, cl2_w, cl2_b, out);
}

// round 4
// speedup vs baseline: 1.7077x; 1.3390x over previous
#include <cuda_runtime.h>
#include <math_constants.h>

#define NQ 6
#define DM 128
#define SEQ 2048
#define CHUNK 16
#define BATCH 128
#define NCHUNK (SEQ / CHUNK)      // 128
#define NROWS (BATCH * NCHUNK)    // 16384

// Scratch (device globals; no allocation allowed)
__device__ float g_params[NROWS * 128];  // per row: fp[60], mp[60], ang[6], pad[2]
__device__ float g_summ[NROWS * 128];    // per row: summ (DM)
__device__ float g_cf[NROWS * 128];      // per row: chunk feature (DM)
__device__ float g_ss[NROWS];            // per row: sequence-attention score

__device__ __forceinline__ float tanh_fast(float x) {
    float y; asm("tanh.approx.f32 %0, %1;" : "=f"(y) : "f"(x)); return y;
}

// ===========================================================================
// Kernel 1: conv1d + LN + chunk attention + ep projection
// one block = 8 chunks (128 seq positions) of one batch row; 256 threads
// h stored d-major: ht[d*130 + p]
// ===========================================================================
struct K1Smem {
    float sx[4][132];
    float ht[128 * 130];
    float w1[128 * 32];
    float cw[128 * 13];
    float lng[128], lnb[128];
    float b1[32], w2[32];
    float scp[4 * 128];
    float sc[128];
    float wgt[128];
    float mv[128], rv[128];
    float summ[8 * 128];
    float epw[768];
    float epb[8];
};

__global__ __launch_bounds__(256) void k1(
    const float* __restrict__ x, const float* __restrict__ conv_w, const float* __restrict__ conv_b,
    const float* __restrict__ ln1_g, const float* __restrict__ ln1_b,
    const float* __restrict__ ca1_w, const float* __restrict__ ca1_b,
    const float* __restrict__ ca2_w, const float* __restrict__ ca2_b,
    const float* __restrict__ ep_w, const float* __restrict__ ep_b)
{
    extern __shared__ char smem_raw[];
    K1Smem& S = *reinterpret_cast<K1Smem*>(smem_raw);

    const int bid = blockIdx.x;
    const int b = bid >> 4;          // batch
    const int g = bid & 15;          // chunk-group (8 chunks)
    const int s_base = g * 128;
    const int t = threadIdx.x;

    // ---- stage weights + input slice ----
    for (int i = t; i < 4096; i += 256) S.w1[i] = ca1_w[i];
    for (int i = t; i < 1536; i += 256) S.cw[(i / 12) * 13 + (i % 12)] = conv_w[i];
    if (t < 128) { S.lng[t] = ln1_g[t]; S.lnb[t] = ln1_b[t]; }
    if (t < 32) { S.b1[t] = ca1_b[t]; S.w2[t] = ca2_w[t]; }
    for (int i = t; i < 768; i += 256) S.epw[i] = ep_w[i];
    if (t < 6) S.epb[t] = ep_b[t];
    for (int i = t; i < 4 * 130; i += 256) {
        int c = i / 130, k = i % 130;
        int s = s_base - 1 + k;
        float v = 0.f;
        if (s >= 0 && s < SEQ) v = x[(b * 4 + c) * SEQ + s];
        S.sx[c][k] = v;
    }
    __syncthreads();

    // ---- conv: thread = (channel d, position half); 64 contiguous positions ----
    const int d = t & 127;
    const int half = t >> 7;
    {
        const int p0c = half * 64;
        float w0[12];
#pragma unroll
        for (int k = 0; k < 12; k++) w0[k] = S.cw[d * 13 + k];
        float bias = conv_b[d];
        float x0[4], x1[4];
#pragma unroll
        for (int c = 0; c < 4; c++) { x0[c] = S.sx[c][p0c]; x1[c] = S.sx[c][p0c + 1]; }
#pragma unroll 4
        for (int p = p0c; p < p0c + 64; p++) {
            float a = bias;
#pragma unroll
            for (int c = 0; c < 4; c++) {
                float x2 = S.sx[c][p + 2];
                a = fmaf(x0[c], w0[c * 3 + 0], a);
                a = fmaf(x1[c], w0[c * 3 + 1], a);
                a = fmaf(x2,    w0[c * 3 + 2], a);
                x0[c] = x1[c]; x1[c] = x2;
            }
            S.ht[d * 130 + p] = a;
        }
    }
    __syncthreads();

    // ---- LayerNorm stats: thread = position ----
    if (t < 128) {
        float s = 0.f, ss = 0.f;
        for (int dd = 0; dd < 128; dd++) {
            float v = S.ht[dd * 130 + t];
            s += v; ss = fmaf(v, v, ss);
        }
        float m = s * (1.f / 128.f);
        float var = ss * (1.f / 128.f) - m * m;
        S.mv[t] = m; S.rv[t] = rsqrtf(var + 1e-5f);
    }
    __syncthreads();
    // ---- normalize in place ----
    for (int i = t; i < 16384; i += 256) {
        int dd = i & 127, p = i >> 7;
        float v = S.ht[dd * 130 + p];
        S.ht[dd * 130 + p] = (v - S.mv[p]) * S.rv[p] * S.lng[dd] + S.lnb[dd];
    }
    __syncthreads();

    // ---- scores: thread = (pos-pair pp, col-group jq of 8) ----
    {
        const int pp = t & 63;
        const int p0 = 2 * pp;
        const int jq = t >> 6;
        const int j0 = 8 * jq;
        float acc[16];
#pragma unroll
        for (int i = 0; i < 16; i++) acc[i] = 0.f;
        for (int dd = 0; dd < 128; dd++) {
            float2 h2 = *reinterpret_cast<const float2*>(&S.ht[dd * 130 + p0]);
            float4 wa = *reinterpret_cast<const float4*>(&S.w1[dd * 32 + j0]);
            float4 wb = *reinterpret_cast<const float4*>(&S.w1[dd * 32 + j0 + 4]);
            acc[0] = fmaf(h2.x, wa.x, acc[0]);  acc[1] = fmaf(h2.x, wa.y, acc[1]);
            acc[2] = fmaf(h2.x, wa.z, acc[2]);  acc[3] = fmaf(h2.x, wa.w, acc[3]);
            acc[4] = fmaf(h2.x, wb.x, acc[4]);  acc[5] = fmaf(h2.x, wb.y, acc[5]);
            acc[6] = fmaf(h2.x, wb.z, acc[6]);  acc[7] = fmaf(h2.x, wb.w, acc[7]);
            acc[8]  = fmaf(h2.y, wa.x, acc[8]);  acc[9]  = fmaf(h2.y, wa.y, acc[9]);
            acc[10] = fmaf(h2.y, wa.z, acc[10]); acc[11] = fmaf(h2.y, wa.w, acc[11]);
            acc[12] = fmaf(h2.y, wb.x, acc[12]); acc[13] = fmaf(h2.y, wb.y, acc[13]);
            acc[14] = fmaf(h2.y, wb.z, acc[14]); acc[15] = fmaf(h2.y, wb.w, acc[15]);
        }
#pragma unroll
        for (int r = 0; r < 2; r++) {
            float sp = 0.f;
#pragma unroll
            for (int k = 0; k < 8; k++)
                sp = fmaf(tanh_fast(acc[r * 8 + k] + S.b1[j0 + k]), S.w2[j0 + k], sp);
            S.scp[jq * 128 + p0 + r] = sp;
        }
    }
    __syncthreads();

    // ---- combine + softmax per chunk (width-16 shuffles) ----
    if (t < 128) {
        float v = S.scp[t] + S.scp[128 + t] + S.scp[256 + t] + S.scp[384 + t] + ca2_b[0];
        float m = v;
#pragma unroll
        for (int o = 8; o; o >>= 1) m = fmaxf(m, __shfl_xor_sync(0xffffffffu, m, o, 16));
        float e = __expf(v - m);
        float sm = e;
#pragma unroll
        for (int o = 8; o; o >>= 1) sm += __shfl_xor_sync(0xffffffffu, sm, o, 16);
        S.wgt[t] = e / sm;
    }
    __syncthreads();

    // ---- weighted sums (8 chunks) ----
    {
        for (int c = 4 * half; c < 4 * half + 4; c++) {
            float a = 0.f;
#pragma unroll
            for (int p = 0; p < 16; p++)
                a = fmaf(S.wgt[c * 16 + p], S.ht[d * 130 + c * 16 + p], a);
            S.summ[c * 128 + d] = a;
            g_summ[(b * 128 + g * 8 + c) * 128 + d] = a;
        }
    }
    __syncthreads();

    // ---- ep projection -> angles (precise tanh: feeds quantum circuit) ----
    if (t < 48) {
        int r = t / 6, j = t % 6;
        float a = S.epb[j];
        for (int dd = 0; dd < 128; dd++)
            a = fmaf(S.summ[r * 128 + dd], S.epw[dd * 6 + j], a);
        g_params[(b * 128 + g * 8 + r) * 128 + 120 + j] =
            tanhf(a) * 3.14159265358979323846f;
    }
}

// ===========================================================================
// Kernel k_pp: pp projection GEMM  (16384 x 128) @ (128 x 120)
// 64 rows/block, 256 blocks; 4x8 register tile per thread
// ===========================================================================
struct KPSmem {
    float w[128 * 128];   // cols 0..119 valid, 120..127 zero
    float s[64 * 129];
};

__global__ __launch_bounds__(256) void k_pp(
    const float* __restrict__ pp_w, const float* __restrict__ pp_b)
{
    extern __shared__ char smem_raw[];
    KPSmem& S = *reinterpret_cast<KPSmem*>(smem_raw);
    const int t = threadIdx.x;
    const int r0 = blockIdx.x * 64;

    for (int i = t; i < 128 * 128; i += 256) S.w[i] = 0.f;
    __syncthreads();
    for (int i = t; i < 128 * 120; i += 256) {
        int dd = i / 120, j = i % 120;
        S.w[dd * 128 + j] = pp_w[i];
    }
    for (int i = t; i < 64 * 128; i += 256) {
        int r = i >> 7, c = i & 127;
        S.s[r * 129 + c] = g_summ[(r0 + r) * 128 + c];
    }
    __syncthreads();

    const int tx = t & 15;         // col group of 8
    const int ty = t >> 4;         // row group of 4
    float acc[4][8];
#pragma unroll
    for (int i = 0; i < 4; i++)
#pragma unroll
        for (int k = 0; k < 8; k++) acc[i][k] = 0.f;

    for (int dd = 0; dd < 128; dd++) {
        float4 wa = *reinterpret_cast<const float4*>(&S.w[dd * 128 + 8 * tx]);
        float4 wb = *reinterpret_cast<const float4*>(&S.w[dd * 128 + 8 * tx + 4]);
        float sv[4];
#pragma unroll
        for (int i = 0; i < 4; i++) sv[i] = S.s[(4 * ty + i) * 129 + dd];
#pragma unroll
        for (int i = 0; i < 4; i++) {
            acc[i][0] = fmaf(sv[i], wa.x, acc[i][0]);
            acc[i][1] = fmaf(sv[i], wa.y, acc[i][1]);
            acc[i][2] = fmaf(sv[i], wa.z, acc[i][2]);
            acc[i][3] = fmaf(sv[i], wa.w, acc[i][3]);
            acc[i][4] = fmaf(sv[i], wb.x, acc[i][4]);
            acc[i][5] = fmaf(sv[i], wb.y, acc[i][5]);
            acc[i][6] = fmaf(sv[i], wb.z, acc[i][6]);
            acc[i][7] = fmaf(sv[i], wb.w, acc[i][7]);
        }
    }
#pragma unroll
    for (int i = 0; i < 4; i++) {
        int gr = r0 + 4 * ty + i;
#pragma unroll
        for (int k = 0; k < 8; k++) {
            int j = 8 * tx + k;
            if (j < 120) g_params[gr * 128 + j] = acc[i][k] + pp_b[j];
        }
    }
}

// ===========================================================================
// Kernel 2: quantum circuit (warp per row) + op projection + LN + SiLU
// ===========================================================================
__device__ __forceinline__ void fused_rxyz(int q, float a, float b_, float g, int lane,
    float& ar0, float& ai0, float& ar1, float& ai1)
{
    float sa, ca; __sincosf(0.5f * a,  &sa, &ca);
    float sb, cb; __sincosf(0.5f * b_, &sb, &cb);
    float sg, cg; __sincosf(0.5f * g,  &sg, &cg);
    float ur = cb * ca, ui = sb * sa;
    float wr = sb * ca, wi = -cb * sa;
    float Pr = cg * ur + sg * ui, Pi = cg * ui - sg * ur;
    float Qr = sg * wi - cg * wr;
    float Qi = cg * wi + sg * wr;

    if (q == 5) {
        float n0r =  Pr * ar0 - Pi * ai0 + Qr * ar1 - Qi * ai1;
        float n0i =  Pr * ai0 + Pi * ar0 + Qr * ai1 + Qi * ar1;
        float n1r = -Qr * ar0 - Qi * ai0 + Pr * ar1 + Pi * ai1;
        float n1i = -Qr * ai0 + Qi * ar0 + Pr * ai1 - Pi * ar1;
        ar0 = n0r; ai0 = n0i; ar1 = n1r; ai1 = n1i;
    } else {
        int m = 1 << (4 - q);
        float br0 = __shfl_xor_sync(0xffffffffu, ar0, m), bi0 = __shfl_xor_sync(0xffffffffu, ai0, m);
        float br1 = __shfl_xor_sync(0xffffffffu, ar1, m), bi1 = __shfl_xor_sync(0xffffffffu, ai1, m);
        int bit = (lane >> (4 - q)) & 1;
        float lPi = bit ? -Pi : Pi;
        float lQr = bit ? -Qr : Qr;
        float n0r = Pr * ar0 - lPi * ai0 + lQr * br0 - Qi * bi0;
        float n0i = Pr * ai0 + lPi * ar0 + lQr * bi0 + Qi * br0;
        float n1r = Pr * ar1 - lPi * ai1 + lQr * br1 - Qi * bi1;
        float n1i = Pr * ai1 + lPi * ar1 + lQr * bi1 + Qi * br1;
        ar0 = n0r; ai0 = n0i; ar1 = n1r; ai1 = n1i;
    }
}

__device__ __forceinline__ void gate_crx(int cq, int tq, float t, int lane,
    float& ar0, float& ai0, float& ar1, float& ai1)
{
    float s, c; __sincosf(0.5f * t, &s, &c);
    if (cq == 5) {
        int m = 1 << (4 - tq);
        float br1 = __shfl_xor_sync(0xffffffffu, ar1, m), bi1 = __shfl_xor_sync(0xffffffffu, ai1, m);
        ar1 = c * ar1 + s * bi1; ai1 = c * ai1 - s * br1;
    } else if (tq == 5) {
        if ((lane >> (4 - cq)) & 1) {
            float nr0 = c * ar0 + s * ai1, ni0 = c * ai0 - s * ar1;
            float nr1 = c * ar1 + s * ai0, ni1 = c * ai1 - s * ar0;
            ar0 = nr0; ai0 = ni0; ar1 = nr1; ai1 = ni1;
        }
    } else {
        int m = 1 << (4 - tq);
        float br0 = __shfl_xor_sync(0xffffffffu, ar0, m), bi0 = __shfl_xor_sync(0xffffffffu, ai0, m);
        float br1 = __shfl_xor_sync(0xffffffffu, ar1, m), bi1 = __shfl_xor_sync(0xffffffffu, ai1, m);
        if ((lane >> (4 - cq)) & 1) {
            ar0 = c * ar0 + s * bi0; ai0 = c * ai0 - s * br0;
            ar1 = c * ar1 + s * bi1; ai1 = c * ai1 - s * br1;
        }
    }
}

__device__ __forceinline__ void ansatz(const float* __restrict__ p, int lane,
    float& ar0, float& ai0, float& ar1, float& ai1)
{
#pragma unroll
    for (int i = 0; i < NQ; i++)
        fused_rxyz(i, p[3 * i], p[3 * i + 1], p[3 * i + 2], lane, ar0, ai0, ar1, ai1);
#pragma unroll
    for (int i = 0; i < NQ; i++)
        gate_crx(i, (i + 1) % NQ, p[18 + i], lane, ar0, ai0, ar1, ai1);
#pragma unroll
    for (int i = NQ - 1; i >= 0; i--)
        gate_crx(i, (i + NQ - 1) % NQ, p[24 + (NQ - 1 - i)], lane, ar0, ai0, ar1, ai1);
}

__global__ __launch_bounds__(256) void k2(
    const float* __restrict__ op_w, const float* __restrict__ op_b,
    const float* __restrict__ ln2_g, const float* __restrict__ ln2_b)
{
    int w = threadIdx.x >> 5;
    int lane = threadIdx.x & 31;
    int r = blockIdx.x * 8 + w;

    __shared__ float s_par[8][128];
#pragma unroll
    for (int j = 0; j < 4; j++)
        s_par[w][lane + 32 * j] = g_params[r * 128 + lane + 32 * j];
    __syncwarp();
    const float* par = s_par[w];
    const float* fp = par;
    const float* mp = par + 60;
    const float* ang = par + 120;

    float ar0, ai0 = 0.f, ar1, ai1 = 0.f;
    {
        float a0 = 1.f, a1 = 1.f;
#pragma unroll
        for (int i = 0; i < 5; i++) {
            float s, c; __sincosf(0.5f * ang[i], &s, &c);
            float f = ((lane >> (4 - i)) & 1) ? s : c;
            a0 *= f; a1 *= f;
        }
        float s, c; __sincosf(0.5f * ang[5], &s, &c);
        ar0 = a0 * c; ar1 = a1 * s;
    }

    ansatz(fp,      lane, ar0, ai0, ar1, ai1);
    ansatz(fp + 30, lane, ar0, ai0, ar1, ai1);
    ansatz(mp,      lane, ar0, ai0, ar1, ai1);
    ansatz(mp + 30, lane, ar0, ai0, ar1, ai1);

    float qv[18];
#pragma unroll
    for (int i = 0; i < NQ; i++) {
        float cr, ci, z;
        float n0 = ar0 * ar0 + ai0 * ai0;
        float n1 = ar1 * ar1 + ai1 * ai1;
        if (i == 5) {
            cr = ar0 * ar1 + ai0 * ai1;
            ci = ar0 * ai1 - ai0 * ar1;
            z  = n0 - n1;
        } else {
            int m = 1 << (4 - i);
            float br0 = __shfl_xor_sync(0xffffffffu, ar0, m), bi0 = __shfl_xor_sync(0xffffffffu, ai0, m);
            float br1 = __shfl_xor_sync(0xffffffffu, ar1, m), bi1 = __shfl_xor_sync(0xffffffffu, ai1, m);
            if (((lane >> (4 - i)) & 1) == 0) {
                cr = ar0 * br0 + ai0 * bi0 + ar1 * br1 + ai1 * bi1;
                ci = ar0 * bi0 - ai0 * br0 + ar1 * bi1 - ai1 * br1;
                z  = n0 + n1;
            } else {
                cr = 0.f; ci = 0.f; z = -(n0 + n1);
            }
        }
#pragma unroll
        for (int o = 16; o; o >>= 1) {
            cr += __shfl_xor_sync(0xffffffffu, cr, o);
            ci += __shfl_xor_sync(0xffffffffu, ci, o);
            z  += __shfl_xor_sync(0xffffffffu, z, o);
        }
        qv[i] = 2.f * cr; qv[6 + i] = 2.f * ci; qv[12 + i] = z;
    }

    float acc[4];
#pragma unroll
    for (int j = 0; j < 4; j++) {
        int d = lane + 32 * j;
        float a = op_b[d];
#pragma unroll
        for (int k = 0; k < 18; k++) a = fmaf(qv[k], __ldg(&op_w[k * 128 + d]), a);
        acc[j] = a;
    }
    float sum = acc[0] + acc[1] + acc[2] + acc[3];
#pragma unroll
    for (int o = 16; o; o >>= 1) sum += __shfl_xor_sync(0xffffffffu, sum, o);
    float mean = sum * (1.f / 128.f);
    float vs = 0.f;
#pragma unroll
    for (int j = 0; j < 4; j++) { float d0 = acc[j] - mean; vs = fmaf(d0, d0, vs); }
#pragma unroll
    for (int o = 16; o; o >>= 1) vs += __shfl_xor_sync(0xffffffffu, vs, o);
    float rstd = rsqrtf(vs * (1.f / 128.f) + 1e-5f);
#pragma unroll
    for (int j = 0; j < 4; j++) {
        int d = lane + 32 * j;
        float xv = (acc[j] - mean) * rstd * ln2_g[d] + ln2_b[d];
        g_cf[r * 128 + d] = xv / (1.f + __expf(-xv));
    }
}

// ===========================================================================
// Kernel k3a: sequence-attention scores as GEMM
// (16384 x 128) @ (128 x 32) -> tanh -> dot(sa2_w) -> g_ss[16384]
// 64 rows/block, 256 blocks; thread = (row ty, col-group tx of 8)
// ===========================================================================
struct K3aSmem {
    float w[128 * 32];
    float s[64 * 129];
    float b1[32], w2[32];
};

__global__ __launch_bounds__(256) void k3a(
    const float* __restrict__ sa1_w, const float* __restrict__ sa1_b,
    const float* __restrict__ sa2_w, const float* __restrict__ sa2_b)
{
    extern __shared__ char smem_raw[];
    K3aSmem& S = *reinterpret_cast<K3aSmem*>(smem_raw);
    const int t = threadIdx.x;
    const int r0 = blockIdx.x * 64;

    for (int i = t; i < 128 * 32; i += 256) S.w[i] = sa1_w[i];
    if (t < 32) { S.b1[t] = sa1_b[t]; S.w2[t] = sa2_w[t]; }
    for (int i = t; i < 64 * 128; i += 256) {
        int r = i >> 7, c = i & 127;
        S.s[r * 129 + c] = g_cf[(r0 + r) * 128 + c];
    }
    __syncthreads();

    const int tx = t & 3;          // col group of 8
    const int ty = t >> 2;         // row (64 rows)
    float acc[8];
#pragma unroll
    for (int k = 0; k < 8; k++) acc[k] = 0.f;

    for (int dd = 0; dd < 128; dd++) {
        float4 wa = *reinterpret_cast<const float4*>(&S.w[dd * 32 + 8 * tx]);
        float4 wb = *reinterpret_cast<const float4*>(&S.w[dd * 32 + 8 * tx + 4]);
        float sv = S.s[ty * 129 + dd];
        acc[0] = fmaf(sv, wa.x, acc[0]);
        acc[1] = fmaf(sv, wa.y, acc[1]);
        acc[2] = fmaf(sv, wa.z, acc[2]);
        acc[3] = fmaf(sv, wa.w, acc[3]);
        acc[4] = fmaf(sv, wb.x, acc[4]);
        acc[5] = fmaf(sv, wb.y, acc[5]);
        acc[6] = fmaf(sv, wb.z, acc[6]);
        acc[7] = fmaf(sv, wb.w, acc[7]);
    }
    float sp = 0.f;
#pragma unroll
    for (int k = 0; k < 8; k++)
        sp = fmaf(tanh_fast(acc[k] + S.b1[8 * tx + k]), S.w2[8 * tx + k], sp);
    sp += __shfl_down_sync(0xffffffffu, sp, 2, 4);
    sp += __shfl_down_sync(0xffffffffu, sp, 1, 4);
    if (tx == 0) g_ss[r0 + ty] = sp + sa2_b[0];
}

// ===========================================================================
// Kernel k3b: per-batch softmax + weighted sum + classifier
// one block (128 threads) per batch row
// ===========================================================================
__global__ __launch_bounds__(128) void k3b(
    const float* __restrict__ cl1_w, const float* __restrict__ cl1_b,
    const float* __restrict__ cl2_w, const float* __restrict__ cl2_b,
    float* __restrict__ out)
{
    int b = blockIdx.x;
    int t = threadIdx.x, lane = t & 31, w = t >> 5;
    const float* cf = g_cf + (size_t)b * NCHUNK * DM;

    __shared__ float red[4];
    __shared__ float sw_s[NCHUNK];
    __shared__ float rep_s[DM];
    __shared__ float u_s[64];

    // softmax over 128 chunks
    float v = g_ss[b * NCHUNK + t];
    float m = v;
#pragma unroll
    for (int o = 16; o; o >>= 1) m = fmaxf(m, __shfl_xor_sync(0xffffffffu, m, o));
    if (lane == 0) red[w] = m;
    __syncthreads();
    m = fmaxf(fmaxf(red[0], red[1]), fmaxf(red[2], red[3]));
    float e = __expf(v - m);
    float sl = e;
#pragma unroll
    for (int o = 16; o; o >>= 1) sl += __shfl_xor_sync(0xffffffffu, sl, o);
    __syncthreads();
    if (lane == 0) red[w] = sl;
    __syncthreads();
    float tot = red[0] + red[1] + red[2] + red[3];
    sw_s[t] = e / tot;
    __syncthreads();

    // rep[d] = sum_n sw[n] * cf[n][d]   (coalesced over d)
    {
        float acc = 0.f;
#pragma unroll 4
        for (int n = 0; n < NCHUNK; n++) acc = fmaf(sw_s[n], __ldg(&cf[n * DM + t]), acc);
        rep_s[t] = acc;
    }
    __syncthreads();

    if (t < 64) {
        float a = cl1_b[t];
        for (int d = 0; d < DM; d++) a = fmaf(rep_s[d], __ldg(&cl1_w[d * 64 + t]), a);
        u_s[t] = a / (1.f + __expf(-a));
    }
    __syncthreads();
    if (t < 2) {
        float a = cl2_b[t];
        for (int j = 0; j < 64; j++) a = fmaf(u_s[j], __ldg(&cl2_w[j * 2 + t]), a);
        out[b * 2 + t] = a;
    }
}

// ===========================================================================
extern "C" void kernel_launch(void* const* d_in, const int* in_sizes, int n_in,
                              void* d_out, int out_size)
{
    const float* x      = (const float*)d_in[0];
    const float* conv_w = (const float*)d_in[1];
    const float* conv_b = (const float*)d_in[2];
    const float* ln1_g  = (const float*)d_in[3];
    const float* ln1_b  = (const float*)d_in[4];
    const float* ca1_w  = (const float*)d_in[5];
    const float* ca1_b  = (const float*)d_in[6];
    const float* ca2_w  = (const float*)d_in[7];
    const float* ca2_b  = (const float*)d_in[8];
    const float* pp_w   = (const float*)d_in[9];
    const float* pp_b   = (const float*)d_in[10];
    const float* ep_w   = (const float*)d_in[11];
    const float* ep_b   = (const float*)d_in[12];
    const float* op_w   = (const float*)d_in[13];
    const float* op_b   = (const float*)d_in[14];
    const float* ln2_g  = (const float*)d_in[15];
    const float* ln2_b  = (const float*)d_in[16];
    const float* sa1_w  = (const float*)d_in[17];
    const float* sa1_b  = (const float*)d_in[18];
    const float* sa2_w  = (const float*)d_in[19];
    const float* sa2_b  = (const float*)d_in[20];
    const float* cl1_w  = (const float*)d_in[21];
    const float* cl1_b  = (const float*)d_in[22];
    const float* cl2_w  = (const float*)d_in[23];
    const float* cl2_b  = (const float*)d_in[24];
    float* out = (float*)d_out;

    cudaFuncSetAttribute(k1, cudaFuncAttributeMaxDynamicSharedMemorySize, (int)sizeof(K1Smem));
    cudaFuncSetAttribute(k_pp, cudaFuncAttributeMaxDynamicSharedMemorySize, (int)sizeof(KPSmem));
    cudaFuncSetAttribute(k3a, cudaFuncAttributeMaxDynamicSharedMemorySize, (int)sizeof(K3aSmem));

    k1<<<BATCH * 16, 256, sizeof(K1Smem)>>>(x, conv_w, conv_b, ln1_g, ln1_b,
                                            ca1_w, ca1_b, ca2_w, ca2_b, ep_w, ep_b);
    k_pp<<<NROWS / 64, 256, sizeof(KPSmem)>>>(pp_w, pp_b);
    k2<<<NROWS / 8, 256>>>(op_w, op_b, ln2_g, ln2_b);
    k3a<<<NROWS / 64, 256, sizeof(K3aSmem)>>>(sa1_w, sa1_b, sa2_w, sa2_b);
    k3b<<<BATCH, 128>>>(cl1_w, cl1_b, cl2_w, cl2_b, out);
}

// round 5
// speedup vs baseline: 1.7788x; 1.0416x over previous
#include <cuda_runtime.h>
#include <math_constants.h>

#define NQ 6
#define DM 128
#define SEQ 2048
#define CHUNK 16
#define BATCH 128
#define NCHUNK (SEQ / CHUNK)      // 128
#define NROWS (BATCH * NCHUNK)    // 16384

// Scratch (device globals; no allocation allowed)
__device__ float g_params[NROWS * 128];  // per row: fp[60], mp[60], ang[6], pad[2]
__device__ float g_summ[NROWS * 128];    // per row: summ (DM)
__device__ float g_cf[NROWS * 128];      // per row: chunk feature (DM)
__device__ float g_ss[NROWS];            // per row: sequence-attention score

__device__ __forceinline__ float tanh_fast(float x) {
    float y; asm("tanh.approx.f32 %0, %1;" : "=f"(y) : "f"(x)); return y;
}

// ===========================================================================
// Kernel 1: conv1d + LN + chunk attention + ep projection
// one block = 8 chunks (128 seq positions) of one batch row; 256 threads
// ===========================================================================
struct K1Smem {
    float sx[4][132];
    float ht[128 * 130];
    float w1[128 * 32];
    float cw[128 * 13];
    float lng[128], lnb[128];
    float b1[32], w2[32];
    float scp[4 * 128];
    float sc[128];
    float wgt[128];
    float mv[128], rv[128];
    float summ[8 * 128];
    float epw[768];
    float epb[8];
};

__global__ __launch_bounds__(256) void k1(
    const float* __restrict__ x, const float* __restrict__ conv_w, const float* __restrict__ conv_b,
    const float* __restrict__ ln1_g, const float* __restrict__ ln1_b,
    const float* __restrict__ ca1_w, const float* __restrict__ ca1_b,
    const float* __restrict__ ca2_w, const float* __restrict__ ca2_b,
    const float* __restrict__ ep_w, const float* __restrict__ ep_b)
{
    extern __shared__ char smem_raw[];
    K1Smem& S = *reinterpret_cast<K1Smem*>(smem_raw);

    const int bid = blockIdx.x;
    const int b = bid >> 4;
    const int g = bid & 15;
    const int s_base = g * 128;
    const int t = threadIdx.x;

    for (int i = t; i < 4096; i += 256) S.w1[i] = ca1_w[i];
    for (int i = t; i < 1536; i += 256) S.cw[(i / 12) * 13 + (i % 12)] = conv_w[i];
    if (t < 128) { S.lng[t] = ln1_g[t]; S.lnb[t] = ln1_b[t]; }
    if (t < 32) { S.b1[t] = ca1_b[t]; S.w2[t] = ca2_w[t]; }
    for (int i = t; i < 768; i += 256) S.epw[i] = ep_w[i];
    if (t < 6) S.epb[t] = ep_b[t];
    for (int i = t; i < 4 * 130; i += 256) {
        int c = i / 130, k = i % 130;
        int s = s_base - 1 + k;
        float v = 0.f;
        if (s >= 0 && s < SEQ) v = x[(b * 4 + c) * SEQ + s];
        S.sx[c][k] = v;
    }
    __syncthreads();

    const int d = t & 127;
    const int half = t >> 7;
    {
        const int p0c = half * 64;
        float w0[12];
#pragma unroll
        for (int k = 0; k < 12; k++) w0[k] = S.cw[d * 13 + k];
        float bias = conv_b[d];
        float x0[4], x1[4];
#pragma unroll
        for (int c = 0; c < 4; c++) { x0[c] = S.sx[c][p0c]; x1[c] = S.sx[c][p0c + 1]; }
#pragma unroll 4
        for (int p = p0c; p < p0c + 64; p++) {
            float a = bias;
#pragma unroll
            for (int c = 0; c < 4; c++) {
                float x2 = S.sx[c][p + 2];
                a = fmaf(x0[c], w0[c * 3 + 0], a);
                a = fmaf(x1[c], w0[c * 3 + 1], a);
                a = fmaf(x2,    w0[c * 3 + 2], a);
                x0[c] = x1[c]; x1[c] = x2;
            }
            S.ht[d * 130 + p] = a;
        }
    }
    __syncthreads();

    if (t < 128) {
        float s = 0.f, ss = 0.f;
        for (int dd = 0; dd < 128; dd++) {
            float v = S.ht[dd * 130 + t];
            s += v; ss = fmaf(v, v, ss);
        }
        float m = s * (1.f / 128.f);
        float var = ss * (1.f / 128.f) - m * m;
        S.mv[t] = m; S.rv[t] = rsqrtf(var + 1e-5f);
    }
    __syncthreads();
    for (int i = t; i < 16384; i += 256) {
        int dd = i & 127, p = i >> 7;
        float v = S.ht[dd * 130 + p];
        S.ht[dd * 130 + p] = (v - S.mv[p]) * S.rv[p] * S.lng[dd] + S.lnb[dd];
    }
    __syncthreads();

    {
        const int pp = t & 63;
        const int p0 = 2 * pp;
        const int jq = t >> 6;
        const int j0 = 8 * jq;
        float acc[16];
#pragma unroll
        for (int i = 0; i < 16; i++) acc[i] = 0.f;
        for (int dd = 0; dd < 128; dd++) {
            float2 h2 = *reinterpret_cast<const float2*>(&S.ht[dd * 130 + p0]);
            float4 wa = *reinterpret_cast<const float4*>(&S.w1[dd * 32 + j0]);
            float4 wb = *reinterpret_cast<const float4*>(&S.w1[dd * 32 + j0 + 4]);
            acc[0] = fmaf(h2.x, wa.x, acc[0]);  acc[1] = fmaf(h2.x, wa.y, acc[1]);
            acc[2] = fmaf(h2.x, wa.z, acc[2]);  acc[3] = fmaf(h2.x, wa.w, acc[3]);
            acc[4] = fmaf(h2.x, wb.x, acc[4]);  acc[5] = fmaf(h2.x, wb.y, acc[5]);
            acc[6] = fmaf(h2.x, wb.z, acc[6]);  acc[7] = fmaf(h2.x, wb.w, acc[7]);
            acc[8]  = fmaf(h2.y, wa.x, acc[8]);  acc[9]  = fmaf(h2.y, wa.y, acc[9]);
            acc[10] = fmaf(h2.y, wa.z, acc[10]); acc[11] = fmaf(h2.y, wa.w, acc[11]);
            acc[12] = fmaf(h2.y, wb.x, acc[12]); acc[13] = fmaf(h2.y, wb.y, acc[13]);
            acc[14] = fmaf(h2.y, wb.z, acc[14]); acc[15] = fmaf(h2.y, wb.w, acc[15]);
        }
#pragma unroll
        for (int r = 0; r < 2; r++) {
            float sp = 0.f;
#pragma unroll
            for (int k = 0; k < 8; k++)
                sp = fmaf(tanh_fast(acc[r * 8 + k] + S.b1[j0 + k]), S.w2[j0 + k], sp);
            S.scp[jq * 128 + p0 + r] = sp;
        }
    }
    __syncthreads();

    if (t < 128) {
        float v = S.scp[t] + S.scp[128 + t] + S.scp[256 + t] + S.scp[384 + t] + ca2_b[0];
        float m = v;
#pragma unroll
        for (int o = 8; o; o >>= 1) m = fmaxf(m, __shfl_xor_sync(0xffffffffu, m, o, 16));
        float e = __expf(v - m);
        float sm = e;
#pragma unroll
        for (int o = 8; o; o >>= 1) sm += __shfl_xor_sync(0xffffffffu, sm, o, 16);
        S.wgt[t] = e / sm;
    }
    __syncthreads();

    {
        for (int c = 4 * half; c < 4 * half + 4; c++) {
            float a = 0.f;
#pragma unroll
            for (int p = 0; p < 16; p++)
                a = fmaf(S.wgt[c * 16 + p], S.ht[d * 130 + c * 16 + p], a);
            S.summ[c * 128 + d] = a;
            g_summ[(b * 128 + g * 8 + c) * 128 + d] = a;
        }
    }
    __syncthreads();

    if (t < 48) {
        int r = t / 6, j = t % 6;
        float a = S.epb[j];
        for (int dd = 0; dd < 128; dd++)
            a = fmaf(S.summ[r * 128 + dd], S.epw[dd * 6 + j], a);
        g_params[(b * 128 + g * 8 + r) * 128 + 120 + j] =
            tanhf(a) * 3.14159265358979323846f;
    }
}

// ===========================================================================
// Kernel k_pp: pp projection GEMM  (16384 x 128) @ (128 x 120)
// ===========================================================================
struct KPSmem {
    float w[128 * 128];
    float s[64 * 129];
};

__global__ __launch_bounds__(256) void k_pp(
    const float* __restrict__ pp_w, const float* __restrict__ pp_b)
{
    extern __shared__ char smem_raw[];
    KPSmem& S = *reinterpret_cast<KPSmem*>(smem_raw);
    const int t = threadIdx.x;
    const int r0 = blockIdx.x * 64;

    for (int i = t; i < 128 * 128; i += 256) S.w[i] = 0.f;
    __syncthreads();
    for (int i = t; i < 128 * 120; i += 256) {
        int dd = i / 120, j = i % 120;
        S.w[dd * 128 + j] = pp_w[i];
    }
    for (int i = t; i < 64 * 128; i += 256) {
        int r = i >> 7, c = i & 127;
        S.s[r * 129 + c] = g_summ[(r0 + r) * 128 + c];
    }
    __syncthreads();

    const int tx = t & 15;
    const int ty = t >> 4;
    float acc[4][8];
#pragma unroll
    for (int i = 0; i < 4; i++)
#pragma unroll
        for (int k = 0; k < 8; k++) acc[i][k] = 0.f;

    for (int dd = 0; dd < 128; dd++) {
        float4 wa = *reinterpret_cast<const float4*>(&S.w[dd * 128 + 8 * tx]);
        float4 wb = *reinterpret_cast<const float4*>(&S.w[dd * 128 + 8 * tx + 4]);
        float sv[4];
#pragma unroll
        for (int i = 0; i < 4; i++) sv[i] = S.s[(4 * ty + i) * 129 + dd];
#pragma unroll
        for (int i = 0; i < 4; i++) {
            acc[i][0] = fmaf(sv[i], wa.x, acc[i][0]);
            acc[i][1] = fmaf(sv[i], wa.y, acc[i][1]);
            acc[i][2] = fmaf(sv[i], wa.z, acc[i][2]);
            acc[i][3] = fmaf(sv[i], wa.w, acc[i][3]);
            acc[i][4] = fmaf(sv[i], wb.x, acc[i][4]);
            acc[i][5] = fmaf(sv[i], wb.y, acc[i][5]);
            acc[i][6] = fmaf(sv[i], wb.z, acc[i][6]);
            acc[i][7] = fmaf(sv[i], wb.w, acc[i][7]);
        }
    }
#pragma unroll
    for (int i = 0; i < 4; i++) {
        int gr = r0 + 4 * ty + i;
#pragma unroll
        for (int k = 0; k < 8; k++) {
            int j = 8 * tx + k;
            if (j < 120) g_params[gr * 128 + j] = acc[i][k] + pp_b[j];
        }
    }
}

// ===========================================================================
// Kernel 2: quantum circuit (warp per row) with precomputed gate coefficients
// smem table per row: fused[24]x{Pr,Pi,Qr,Qi} @0, crx[48]x{c,s} @96, init[6]x{c,s} @192
// ===========================================================================
#define TBL_STRIDE 208

__device__ __forceinline__ void apply_su2(int q, float Pr, float Pi, float Qr, float Qi,
    int lane, float& ar0, float& ai0, float& ar1, float& ai1)
{
    if (q == 5) {
        float n0r =  Pr * ar0 - Pi * ai0 + Qr * ar1 - Qi * ai1;
        float n0i =  Pr * ai0 + Pi * ar0 + Qr * ai1 + Qi * ar1;
        float n1r = -Qr * ar0 - Qi * ai0 + Pr * ar1 + Pi * ai1;
        float n1i = -Qr * ai0 + Qi * ar0 + Pr * ai1 - Pi * ar1;
        ar0 = n0r; ai0 = n0i; ar1 = n1r; ai1 = n1i;
    } else {
        int m = 1 << (4 - q);
        float br0 = __shfl_xor_sync(0xffffffffu, ar0, m), bi0 = __shfl_xor_sync(0xffffffffu, ai0, m);
        float br1 = __shfl_xor_sync(0xffffffffu, ar1, m), bi1 = __shfl_xor_sync(0xffffffffu, ai1, m);
        int bit = (lane >> (4 - q)) & 1;
        float lPi = bit ? -Pi : Pi;
        float lQr = bit ? -Qr : Qr;
        float n0r = Pr * ar0 - lPi * ai0 + lQr * br0 - Qi * bi0;
        float n0i = Pr * ai0 + lPi * ar0 + lQr * bi0 + Qi * br0;
        float n1r = Pr * ar1 - lPi * ai1 + lQr * br1 - Qi * bi1;
        float n1i = Pr * ai1 + lPi * ar1 + lQr * bi1 + Qi * br1;
        ar0 = n0r; ai0 = n0i; ar1 = n1r; ai1 = n1i;
    }
}

__device__ __forceinline__ void apply_crx(int cq, int tq, float c, float s,
    int lane, float& ar0, float& ai0, float& ar1, float& ai1)
{
    if (cq == 5) {
        int m = 1 << (4 - tq);
        float br1 = __shfl_xor_sync(0xffffffffu, ar1, m), bi1 = __shfl_xor_sync(0xffffffffu, ai1, m);
        ar1 = c * ar1 + s * bi1; ai1 = c * ai1 - s * br1;
    } else if (tq == 5) {
        if ((lane >> (4 - cq)) & 1) {
            float nr0 = c * ar0 + s * ai1, ni0 = c * ai0 - s * ar1;
            float nr1 = c * ar1 + s * ai0, ni1 = c * ai1 - s * ar0;
            ar0 = nr0; ai0 = ni0; ar1 = nr1; ai1 = ni1;
        }
    } else {
        int m = 1 << (4 - tq);
        float br0 = __shfl_xor_sync(0xffffffffu, ar0, m), bi0 = __shfl_xor_sync(0xffffffffu, ai0, m);
        float br1 = __shfl_xor_sync(0xffffffffu, ar1, m), bi1 = __shfl_xor_sync(0xffffffffu, ai1, m);
        if ((lane >> (4 - cq)) & 1) {
            ar0 = c * ar0 + s * bi0; ai0 = c * ai0 - s * br0;
            ar1 = c * ar1 + s * bi1; ai1 = c * ai1 - s * br1;
        }
    }
}

__global__ __launch_bounds__(256) void k2(
    const float* __restrict__ op_w, const float* __restrict__ op_b,
    const float* __restrict__ ln2_g, const float* __restrict__ ln2_b)
{
    int w = threadIdx.x >> 5;
    int lane = threadIdx.x & 31;
    int r = blockIdx.x * 8 + w;

    __shared__ float s_par[8][128];
    __shared__ __align__(16) float s_tbl[8][TBL_STRIDE];
#pragma unroll
    for (int j = 0; j < 4; j++)
        s_par[w][lane + 32 * j] = g_params[r * 128 + lane + 32 * j];
    __syncwarp();
    const float* par = s_par[w];
    float* T = s_tbl[w];

    // ---- phase A: distribute coefficient computation across lanes ----
    if (lane < 24) {
        int a = lane / 6, i = lane % 6;
        const float* base = par + (a >> 1) * 60 + (a & 1) * 30;
        float sa, ca; __sincosf(0.5f * base[3 * i],     &sa, &ca);
        float sb, cb; __sincosf(0.5f * base[3 * i + 1], &sb, &cb);
        float sg, cg; __sincosf(0.5f * base[3 * i + 2], &sg, &cg);
        float ur = cb * ca, ui = sb * sa;
        float wr = sb * ca, wi = -cb * sa;
        T[4 * lane + 0] = cg * ur + sg * ui;   // Pr
        T[4 * lane + 1] = cg * ui - sg * ur;   // Pi
        T[4 * lane + 2] = sg * wi - cg * wr;   // Qr
        T[4 * lane + 3] = cg * wi + sg * wr;   // Qi
    }
    for (int gg = lane; gg < 48; gg += 32) {
        int a = gg / 12, j = gg % 12;
        const float* base = par + (a >> 1) * 60 + (a & 1) * 30;
        float s, c; __sincosf(0.5f * base[18 + j], &s, &c);
        T[96 + 2 * gg] = c; T[97 + 2 * gg] = s;
    }
    if (lane < 6) {
        float s, c; __sincosf(0.5f * par[120 + lane], &s, &c);
        T[192 + 2 * lane] = c; T[193 + 2 * lane] = s;
    }
    __syncwarp();

    // ---- initial product state after per-qubit RY on |0> ----
    float ar0, ai0 = 0.f, ar1, ai1 = 0.f;
    {
        float a0 = 1.f, a1 = 1.f;
#pragma unroll
        for (int i = 0; i < 5; i++) {
            float c = T[192 + 2 * i], s = T[193 + 2 * i];
            float f = ((lane >> (4 - i)) & 1) ? s : c;
            a0 *= f; a1 *= f;
        }
        ar0 = a0 * T[202]; ar1 = a1 * T[203];
    }

    // ---- 4 ansatz applications from the table ----
#pragma unroll
    for (int a = 0; a < 4; a++) {
        const float* F = T + a * 24;
        const float* C = T + 96 + a * 24;
#pragma unroll
        for (int i = 0; i < NQ; i++) {
            float4 pq = *reinterpret_cast<const float4*>(&F[4 * i]);
            apply_su2(i, pq.x, pq.y, pq.z, pq.w, lane, ar0, ai0, ar1, ai1);
        }
#pragma unroll
        for (int j = 0; j < 6; j++) {
            float2 cs = *reinterpret_cast<const float2*>(&C[2 * j]);
            apply_crx(j, (j + 1) % NQ, cs.x, cs.y, lane, ar0, ai0, ar1, ai1);
        }
#pragma unroll
        for (int j = 6; j < 12; j++) {
            float2 cs = *reinterpret_cast<const float2*>(&C[2 * j]);
            int i = 11 - j;
            apply_crx(i, (i + NQ - 1) % NQ, cs.x, cs.y, lane, ar0, ai0, ar1, ai1);
        }
    }

    // ---- measurements ----
    float qv[18];
#pragma unroll
    for (int i = 0; i < NQ; i++) {
        float cr, ci, z;
        float n0 = ar0 * ar0 + ai0 * ai0;
        float n1 = ar1 * ar1 + ai1 * ai1;
        if (i == 5) {
            cr = ar0 * ar1 + ai0 * ai1;
            ci = ar0 * ai1 - ai0 * ar1;
            z  = n0 - n1;
        } else {
            int m = 1 << (4 - i);
            float br0 = __shfl_xor_sync(0xffffffffu, ar0, m), bi0 = __shfl_xor_sync(0xffffffffu, ai0, m);
            float br1 = __shfl_xor_sync(0xffffffffu, ar1, m), bi1 = __shfl_xor_sync(0xffffffffu, ai1, m);
            if (((lane >> (4 - i)) & 1) == 0) {
                cr = ar0 * br0 + ai0 * bi0 + ar1 * br1 + ai1 * bi1;
                ci = ar0 * bi0 - ai0 * br0 + ar1 * bi1 - ai1 * br1;
                z  = n0 + n1;
            } else {
                cr = 0.f; ci = 0.f; z = -(n0 + n1);
            }
        }
#pragma unroll
        for (int o = 16; o; o >>= 1) {
            cr += __shfl_xor_sync(0xffffffffu, cr, o);
            ci += __shfl_xor_sync(0xffffffffu, ci, o);
            z  += __shfl_xor_sync(0xffffffffu, z, o);
        }
        qv[i] = 2.f * cr; qv[6 + i] = 2.f * ci; qv[12 + i] = z;
    }

    // ---- op projection + LN + SiLU ----
    float acc[4];
#pragma unroll
    for (int j = 0; j < 4; j++) {
        int d = lane + 32 * j;
        float a = op_b[d];
#pragma unroll
        for (int k = 0; k < 18; k++) a = fmaf(qv[k], __ldg(&op_w[k * 128 + d]), a);
        acc[j] = a;
    }
    float sum = acc[0] + acc[1] + acc[2] + acc[3];
#pragma unroll
    for (int o = 16; o; o >>= 1) sum += __shfl_xor_sync(0xffffffffu, sum, o);
    float mean = sum * (1.f / 128.f);
    float vs = 0.f;
#pragma unroll
    for (int j = 0; j < 4; j++) { float d0 = acc[j] - mean; vs = fmaf(d0, d0, vs); }
#pragma unroll
    for (int o = 16; o; o >>= 1) vs += __shfl_xor_sync(0xffffffffu, vs, o);
    float rstd = rsqrtf(vs * (1.f / 128.f) + 1e-5f);
#pragma unroll
    for (int j = 0; j < 4; j++) {
        int d = lane + 32 * j;
        float xv = (acc[j] - mean) * rstd * ln2_g[d] + ln2_b[d];
        g_cf[r * 128 + d] = xv / (1.f + __expf(-xv));
    }
}

// ===========================================================================
// Kernel k3a: sequence-attention scores as GEMM -> g_ss[16384]
// ===========================================================================
struct K3aSmem {
    float w[128 * 32];
    float s[64 * 129];
    float b1[32], w2[32];
};

__global__ __launch_bounds__(256) void k3a(
    const float* __restrict__ sa1_w, const float* __restrict__ sa1_b,
    const float* __restrict__ sa2_w, const float* __restrict__ sa2_b)
{
    extern __shared__ char smem_raw[];
    K3aSmem& S = *reinterpret_cast<K3aSmem*>(smem_raw);
    const int t = threadIdx.x;
    const int r0 = blockIdx.x * 64;

    for (int i = t; i < 128 * 32; i += 256) S.w[i] = sa1_w[i];
    if (t < 32) { S.b1[t] = sa1_b[t]; S.w2[t] = sa2_w[t]; }
    for (int i = t; i < 64 * 128; i += 256) {
        int r = i >> 7, c = i & 127;
        S.s[r * 129 + c] = g_cf[(r0 + r) * 128 + c];
    }
    __syncthreads();

    const int tx = t & 3;
    const int ty = t >> 2;
    float acc[8];
#pragma unroll
    for (int k = 0; k < 8; k++) acc[k] = 0.f;

#pragma unroll 4
    for (int dd = 0; dd < 128; dd++) {
        float4 wa = *reinterpret_cast<const float4*>(&S.w[dd * 32 + 8 * tx]);
        float4 wb = *reinterpret_cast<const float4*>(&S.w[dd * 32 + 8 * tx + 4]);
        float sv = S.s[ty * 129 + dd];
        acc[0] = fmaf(sv, wa.x, acc[0]);
        acc[1] = fmaf(sv, wa.y, acc[1]);
        acc[2] = fmaf(sv, wa.z, acc[2]);
        acc[3] = fmaf(sv, wa.w, acc[3]);
        acc[4] = fmaf(sv, wb.x, acc[4]);
        acc[5] = fmaf(sv, wb.y, acc[5]);
        acc[6] = fmaf(sv, wb.z, acc[6]);
        acc[7] = fmaf(sv, wb.w, acc[7]);
    }
    float sp = 0.f;
#pragma unroll
    for (int k = 0; k < 8; k++)
        sp = fmaf(tanh_fast(acc[k] + S.b1[8 * tx + k]), S.w2[8 * tx + k], sp);
    sp += __shfl_down_sync(0xffffffffu, sp, 2, 4);
    sp += __shfl_down_sync(0xffffffffu, sp, 1, 4);
    if (tx == 0) g_ss[r0 + ty] = sp + sa2_b[0];
}

// ===========================================================================
// Kernel k3b: per-batch softmax + weighted sum + classifier (512 threads)
// ===========================================================================
__global__ __launch_bounds__(512) void k3b(
    const float* __restrict__ cl1_w, const float* __restrict__ cl1_b,
    const float* __restrict__ cl2_w, const float* __restrict__ cl2_b,
    float* __restrict__ out)
{
    int b = blockIdx.x;
    int t = threadIdx.x, lane = t & 31, w = t >> 5;
    const float* cf = g_cf + (size_t)b * NCHUNK * DM;

    __shared__ float red[8];
    __shared__ float sw_s[NCHUNK];
    __shared__ float part[4][DM];
    __shared__ float rep_s[DM];
    __shared__ float u_s[64];

    // softmax over 128 chunks (first 4 warps)
    float v = 0.f, e = 0.f;
    if (t < 128) {
        v = g_ss[b * NCHUNK + t];
        float m = v;
#pragma unroll
        for (int o = 16; o; o >>= 1) m = fmaxf(m, __shfl_xor_sync(0xffffffffu, m, o));
        if (lane == 0) red[w] = m;
    }
    __syncthreads();
    float mg = fmaxf(fmaxf(red[0], red[1]), fmaxf(red[2], red[3]));
    if (t < 128) {
        e = __expf(v - mg);
        float sl = e;
#pragma unroll
        for (int o = 16; o; o >>= 1) sl += __shfl_xor_sync(0xffffffffu, sl, o);
        if (lane == 0) red[4 + w] = sl;
    }
    __syncthreads();
    float tot = red[4] + red[5] + red[6] + red[7];
    if (t < 128) sw_s[t] = e / tot;
    __syncthreads();

    // weighted sum: quarter q handles 32 chunks for channel d
    {
        int d = t & 127, q = t >> 7;
        float acc = 0.f;
#pragma unroll 4
        for (int n = q * 32; n < q * 32 + 32; n++)
            acc = fmaf(sw_s[n], __ldg(&cf[n * DM + d]), acc);
        part[q][d] = acc;
    }
    __syncthreads();
    if (t < 128) rep_s[t] = part[0][t] + part[1][t] + part[2][t] + part[3][t];
    __syncthreads();

    if (t < 64) {
        float a = cl1_b[t];
#pragma unroll 4
        for (int d = 0; d < DM; d++) a = fmaf(rep_s[d], __ldg(&cl1_w[d * 64 + t]), a);
        u_s[t] = a / (1.f + __expf(-a));
    }
    __syncthreads();
    if (t < 2) {
        float a = cl2_b[t];
#pragma unroll 4
        for (int j = 0; j < 64; j++) a = fmaf(u_s[j], __ldg(&cl2_w[j * 2 + t]), a);
        out[b * 2 + t] = a;
    }
}

// ===========================================================================
extern "C" void kernel_launch(void* const* d_in, const int* in_sizes, int n_in,
                              void* d_out, int out_size)
{
    const float* x      = (const float*)d_in[0];
    const float* conv_w = (const float*)d_in[1];
    const float* conv_b = (const float*)d_in[2];
    const float* ln1_g  = (const float*)d_in[3];
    const float* ln1_b  = (const float*)d_in[4];
    const float* ca1_w  = (const float*)d_in[5];
    const float* ca1_b  = (const float*)d_in[6];
    const float* ca2_w  = (const float*)d_in[7];
    const float* ca2_b  = (const float*)d_in[8];
    const float* pp_w   = (const float*)d_in[9];
    const float* pp_b   = (const float*)d_in[10];
    const float* ep_w   = (const float*)d_in[11];
    const float* ep_b   = (const float*)d_in[12];
    const float* op_w   = (const float*)d_in[13];
    const float* op_b   = (const float*)d_in[14];
    const float* ln2_g  = (const float*)d_in[15];
    const float* ln2_b  = (const float*)d_in[16];
    const float* sa1_w  = (const float*)d_in[17];
    const float* sa1_b  = (const float*)d_in[18];
    const float* sa2_w  = (const float*)d_in[19];
    const float* sa2_b  = (const float*)d_in[20];
    const float* cl1_w  = (const float*)d_in[21];
    const float* cl1_b  = (const float*)d_in[22];
    const float* cl2_w  = (const float*)d_in[23];
    const float* cl2_b  = (const float*)d_in[24];
    float* out = (float*)d_out;

    cudaFuncSetAttribute(k1, cudaFuncAttributeMaxDynamicSharedMemorySize, (int)sizeof(K1Smem));
    cudaFuncSetAttribute(k_pp, cudaFuncAttributeMaxDynamicSharedMemorySize, (int)sizeof(KPSmem));
    cudaFuncSetAttribute(k3a, cudaFuncAttributeMaxDynamicSharedMemorySize, (int)sizeof(K3aSmem));

    k1<<<BATCH * 16, 256, sizeof(K1Smem)>>>(x, conv_w, conv_b, ln1_g, ln1_b,
                                            ca1_w, ca1_b, ca2_w, ca2_b, ep_w, ep_b);
    k_pp<<<NROWS / 64, 256, sizeof(KPSmem)>>>(pp_w, pp_b);
    k2<<<NROWS / 8, 256>>>(op_w, op_b, ln2_g, ln2_b);
    k3a<<<NROWS / 64, 256, sizeof(K3aSmem)>>>(sa1_w, sa1_b, sa2_w, sa2_b);
    k3b<<<BATCH, 512>>>(cl1_w, cl1_b, cl2_w, cl2_b, out);
}

// round 6
// speedup vs baseline: 1.9256x; 1.0825x over previous
#include <cuda_runtime.h>
#include <math_constants.h>

#define NQ 6
#define DM 128
#define SEQ 2048
#define CHUNK 16
#define BATCH 128
#define NCHUNK (SEQ / CHUNK)      // 128
#define NROWS (BATCH * NCHUNK)    // 16384

typedef unsigned long long ull;

// Scratch (device globals; no allocation allowed)
__device__ float g_params[NROWS * 128];  // per row: fp[60], mp[60], ang[6], pad[2]
__device__ float g_summ[NROWS * 128];    // per row: summ (DM)
__device__ float g_cf[NROWS * 128];      // per row: chunk feature (DM)
__device__ float g_ss[NROWS];            // per row: sequence-attention score

__device__ __forceinline__ float tanh_fast(float x) {
    float y; asm("tanh.approx.f32 %0, %1;" : "=f"(y) : "f"(x)); return y;
}

// ---- packed fp32x2 helpers (Blackwell FFMA2 path; exact fp32 per half) ----
__device__ __forceinline__ ull pack2(float lo, float hi) {
    ull r; asm("mov.b64 %0, {%1, %2};" : "=l"(r) : "f"(lo), "f"(hi)); return r;
}
__device__ __forceinline__ void fma2(ull& d, ull a, ull b) {
    asm("fma.rn.f32x2 %0, %1, %2, %3;" : "=l"(d) : "l"(a), "l"(b), "l"(d));
}
__device__ __forceinline__ float2 unpack2(ull v) {
    float2 f; asm("mov.b64 {%0, %1}, %2;" : "=f"(f.x), "=f"(f.y) : "l"(v)); return f;
}

// ===========================================================================
// Kernel 1: conv1d + LN + chunk attention + ep projection
// one block = 8 chunks (128 seq positions) of one batch row; 256 threads
// ===========================================================================
struct K1Smem {
    float sx[4][132];
    float ht[128 * 130];
    float w1[128 * 32];
    float cw[128 * 13];
    float lng[128], lnb[128];
    float b1[32], w2[32];
    float scp[4 * 128];
    float wgt[128];
    float mv[128], rv[128];
    float summ[8 * 128];
    float epw[768];
    float epb[8];
};

__global__ __launch_bounds__(256) void k1(
    const float* __restrict__ x, const float* __restrict__ conv_w, const float* __restrict__ conv_b,
    const float* __restrict__ ln1_g, const float* __restrict__ ln1_b,
    const float* __restrict__ ca1_w, const float* __restrict__ ca1_b,
    const float* __restrict__ ca2_w, const float* __restrict__ ca2_b,
    const float* __restrict__ ep_w, const float* __restrict__ ep_b)
{
    extern __shared__ char smem_raw[];
    K1Smem& S = *reinterpret_cast<K1Smem*>(smem_raw);

    const int bid = blockIdx.x;
    const int b = bid >> 4;
    const int g = bid & 15;
    const int s_base = g * 128;
    const int t = threadIdx.x;

    for (int i = t; i < 4096; i += 256) S.w1[i] = ca1_w[i];
    for (int i = t; i < 1536; i += 256) S.cw[(i / 12) * 13 + (i % 12)] = conv_w[i];
    if (t < 128) { S.lng[t] = ln1_g[t]; S.lnb[t] = ln1_b[t]; }
    if (t < 32) { S.b1[t] = ca1_b[t]; S.w2[t] = ca2_w[t]; }
    for (int i = t; i < 768; i += 256) S.epw[i] = ep_w[i];
    if (t < 6) S.epb[t] = ep_b[t];
    for (int i = t; i < 4 * 130; i += 256) {
        int c = i / 130, k = i % 130;
        int s = s_base - 1 + k;
        float v = 0.f;
        if (s >= 0 && s < SEQ) v = x[(b * 4 + c) * SEQ + s];
        S.sx[c][k] = v;
    }
    __syncthreads();

    const int d = t & 127;
    const int half = t >> 7;
    // ---- conv (packed 2 positions per step) ----
    {
        const int p0c = half * 64;
        ull wp[12];
#pragma unroll
        for (int k = 0; k < 12; k++) { float wv = S.cw[d * 13 + k]; wp[k] = pack2(wv, wv); }
        float bv = conv_b[d];
        ull bias2 = pack2(bv, bv);
        float xs0[4], xs1[4];
#pragma unroll
        for (int c = 0; c < 4; c++) { xs0[c] = S.sx[c][p0c]; xs1[c] = S.sx[c][p0c + 1]; }
#pragma unroll 4
        for (int p = p0c; p < p0c + 64; p += 2) {
            ull a2 = bias2;
#pragma unroll
            for (int c = 0; c < 4; c++) {
                float x2 = S.sx[c][p + 2], x3 = S.sx[c][p + 3];
                fma2(a2, pack2(xs0[c], xs1[c]), wp[c * 3 + 0]);
                fma2(a2, pack2(xs1[c], x2),     wp[c * 3 + 1]);
                fma2(a2, pack2(x2, x3),         wp[c * 3 + 2]);
                xs0[c] = x2; xs1[c] = x3;
            }
            float2 f = unpack2(a2);
            S.ht[d * 130 + p] = f.x;
            S.ht[d * 130 + p + 1] = f.y;
        }
    }
    __syncthreads();

    // ---- LayerNorm stats: thread = position ----
    if (t < 128) {
        float s = 0.f, ss = 0.f;
        for (int dd = 0; dd < 128; dd++) {
            float v = S.ht[dd * 130 + t];
            s += v; ss = fmaf(v, v, ss);
        }
        float m = s * (1.f / 128.f);
        float var = ss * (1.f / 128.f) - m * m;
        S.mv[t] = m; S.rv[t] = rsqrtf(var + 1e-5f);
    }
    __syncthreads();
    for (int i = t; i < 16384; i += 256) {
        int dd = i & 127, p = i >> 7;
        float v = S.ht[dd * 130 + p];
        S.ht[dd * 130 + p] = (v - S.mv[p]) * S.rv[p] * S.lng[dd] + S.lnb[dd];
    }
    __syncthreads();

    // ---- scores: thread = (pos-pair, col-group of 8); packed col-pairs ----
    {
        const int pp = t & 63;
        const int p0 = 2 * pp;
        const int jq = t >> 6;
        const int j0 = 8 * jq;
        ull acc2[2][4];
#pragma unroll
        for (int r = 0; r < 2; r++)
#pragma unroll
            for (int c = 0; c < 4; c++) acc2[r][c] = 0ull;
        for (int dd = 0; dd < 128; dd++) {
            float2 h2 = *reinterpret_cast<const float2*>(&S.ht[dd * 130 + p0]);
            ull hx = pack2(h2.x, h2.x), hy = pack2(h2.y, h2.y);
            ulonglong2 wpa = *reinterpret_cast<const ulonglong2*>(&S.w1[dd * 32 + j0]);
            ulonglong2 wpb = *reinterpret_cast<const ulonglong2*>(&S.w1[dd * 32 + j0 + 4]);
            fma2(acc2[0][0], hx, wpa.x); fma2(acc2[0][1], hx, wpa.y);
            fma2(acc2[0][2], hx, wpb.x); fma2(acc2[0][3], hx, wpb.y);
            fma2(acc2[1][0], hy, wpa.x); fma2(acc2[1][1], hy, wpa.y);
            fma2(acc2[1][2], hy, wpb.x); fma2(acc2[1][3], hy, wpb.y);
        }
#pragma unroll
        for (int r = 0; r < 2; r++) {
            float sp = 0.f;
#pragma unroll
            for (int c = 0; c < 4; c++) {
                float2 f = unpack2(acc2[r][c]);
                sp = fmaf(tanh_fast(f.x + S.b1[j0 + 2 * c]),     S.w2[j0 + 2 * c],     sp);
                sp = fmaf(tanh_fast(f.y + S.b1[j0 + 2 * c + 1]), S.w2[j0 + 2 * c + 1], sp);
            }
            S.scp[jq * 128 + p0 + r] = sp;
        }
    }
    __syncthreads();

    if (t < 128) {
        float v = S.scp[t] + S.scp[128 + t] + S.scp[256 + t] + S.scp[384 + t] + ca2_b[0];
        float m = v;
#pragma unroll
        for (int o = 8; o; o >>= 1) m = fmaxf(m, __shfl_xor_sync(0xffffffffu, m, o, 16));
        float e = __expf(v - m);
        float sm = e;
#pragma unroll
        for (int o = 8; o; o >>= 1) sm += __shfl_xor_sync(0xffffffffu, sm, o, 16);
        S.wgt[t] = e / sm;
    }
    __syncthreads();

    {
        for (int c = 4 * half; c < 4 * half + 4; c++) {
            float a = 0.f;
#pragma unroll
            for (int p = 0; p < 16; p++)
                a = fmaf(S.wgt[c * 16 + p], S.ht[d * 130 + c * 16 + p], a);
            S.summ[c * 128 + d] = a;
            g_summ[(b * 128 + g * 8 + c) * 128 + d] = a;
        }
    }
    __syncthreads();

    if (t < 48) {
        int r = t / 6, j = t % 6;
        float a = S.epb[j];
        for (int dd = 0; dd < 128; dd++)
            a = fmaf(S.summ[r * 128 + dd], S.epw[dd * 6 + j], a);
        g_params[(b * 128 + g * 8 + r) * 128 + 120 + j] =
            tanhf(a) * 3.14159265358979323846f;
    }
}

// ===========================================================================
// Kernel k_pp: pp projection GEMM  (16384 x 128) @ (128 x 120), f32x2 packed
// ===========================================================================
struct KPSmem {
    float w[128 * 128];
    float s[64 * 129];
};

__global__ __launch_bounds__(256) void k_pp(
    const float* __restrict__ pp_w, const float* __restrict__ pp_b)
{
    extern __shared__ char smem_raw[];
    KPSmem& S = *reinterpret_cast<KPSmem*>(smem_raw);
    const int t = threadIdx.x;
    const int r0 = blockIdx.x * 64;

    for (int i = t; i < 128 * 128; i += 256) S.w[i] = 0.f;
    __syncthreads();
    for (int i = t; i < 128 * 120; i += 256) {
        int dd = i / 120, j = i % 120;
        S.w[dd * 128 + j] = pp_w[i];
    }
    for (int i = t; i < 64 * 128; i += 256) {
        int r = i >> 7, c = i & 127;
        S.s[r * 129 + c] = g_summ[(r0 + r) * 128 + c];
    }
    __syncthreads();

    const int tx = t & 15;
    const int ty = t >> 4;
    ull acc2[4][4];
#pragma unroll
    for (int i = 0; i < 4; i++)
#pragma unroll
        for (int c = 0; c < 4; c++) acc2[i][c] = 0ull;

    for (int dd = 0; dd < 128; dd++) {
        ulonglong2 wpa = *reinterpret_cast<const ulonglong2*>(&S.w[dd * 128 + 8 * tx]);
        ulonglong2 wpb = *reinterpret_cast<const ulonglong2*>(&S.w[dd * 128 + 8 * tx + 4]);
        ull sv2[4];
#pragma unroll
        for (int i = 0; i < 4; i++) {
            float sv = S.s[(4 * ty + i) * 129 + dd];
            sv2[i] = pack2(sv, sv);
        }
#pragma unroll
        for (int i = 0; i < 4; i++) {
            fma2(acc2[i][0], sv2[i], wpa.x);
            fma2(acc2[i][1], sv2[i], wpa.y);
            fma2(acc2[i][2], sv2[i], wpb.x);
            fma2(acc2[i][3], sv2[i], wpb.y);
        }
    }
#pragma unroll
    for (int i = 0; i < 4; i++) {
        int gr = r0 + 4 * ty + i;
#pragma unroll
        for (int c = 0; c < 4; c++) {
            float2 f = unpack2(acc2[i][c]);
            int j = 8 * tx + 2 * c;
            if (j < 120)     g_params[gr * 128 + j]     = f.x + pp_b[j];
            if (j + 1 < 120) g_params[gr * 128 + j + 1] = f.y + pp_b[j + 1];
        }
    }
}

// ===========================================================================
// Kernel 2: quantum circuit (warp per row) + op projection + LN + SiLU
//           + fused sequence-attention score (replaces old k3a)
// ===========================================================================
#define TBL_STRIDE 208

__device__ __forceinline__ void apply_su2(int q, float Pr, float Pi, float Qr, float Qi,
    int lane, float& ar0, float& ai0, float& ar1, float& ai1)
{
    if (q == 5) {
        float n0r =  Pr * ar0 - Pi * ai0 + Qr * ar1 - Qi * ai1;
        float n0i =  Pr * ai0 + Pi * ar0 + Qr * ai1 + Qi * ar1;
        float n1r = -Qr * ar0 - Qi * ai0 + Pr * ar1 + Pi * ai1;
        float n1i = -Qr * ai0 + Qi * ar0 + Pr * ai1 - Pi * ar1;
        ar0 = n0r; ai0 = n0i; ar1 = n1r; ai1 = n1i;
    } else {
        int m = 1 << (4 - q);
        float br0 = __shfl_xor_sync(0xffffffffu, ar0, m), bi0 = __shfl_xor_sync(0xffffffffu, ai0, m);
        float br1 = __shfl_xor_sync(0xffffffffu, ar1, m), bi1 = __shfl_xor_sync(0xffffffffu, ai1, m);
        int bit = (lane >> (4 - q)) & 1;
        float lPi = bit ? -Pi : Pi;
        float lQr = bit ? -Qr : Qr;
        float n0r = Pr * ar0 - lPi * ai0 + lQr * br0 - Qi * bi0;
        float n0i = Pr * ai0 + lPi * ar0 + lQr * bi0 + Qi * br0;
        float n1r = Pr * ar1 - lPi * ai1 + lQr * br1 - Qi * bi1;
        float n1i = Pr * ai1 + lPi * ar1 + lQr * bi1 + Qi * br1;
        ar0 = n0r; ai0 = n0i; ar1 = n1r; ai1 = n1i;
    }
}

__device__ __forceinline__ void apply_crx(int cq, int tq, float c, float s,
    int lane, float& ar0, float& ai0, float& ar1, float& ai1)
{
    if (cq == 5) {
        int m = 1 << (4 - tq);
        float br1 = __shfl_xor_sync(0xffffffffu, ar1, m), bi1 = __shfl_xor_sync(0xffffffffu, ai1, m);
        ar1 = c * ar1 + s * bi1; ai1 = c * ai1 - s * br1;
    } else if (tq == 5) {
        if ((lane >> (4 - cq)) & 1) {
            float nr0 = c * ar0 + s * ai1, ni0 = c * ai0 - s * ar1;
            float nr1 = c * ar1 + s * ai0, ni1 = c * ai1 - s * ar0;
            ar0 = nr0; ai0 = ni0; ar1 = nr1; ai1 = ni1;
        }
    } else {
        int m = 1 << (4 - tq);
        float br0 = __shfl_xor_sync(0xffffffffu, ar0, m), bi0 = __shfl_xor_sync(0xffffffffu, ai0, m);
        float br1 = __shfl_xor_sync(0xffffffffu, ar1, m), bi1 = __shfl_xor_sync(0xffffffffu, ai1, m);
        if ((lane >> (4 - cq)) & 1) {
            ar0 = c * ar0 + s * bi0; ai0 = c * ai0 - s * br0;
            ar1 = c * ar1 + s * bi1; ai1 = c * ai1 - s * br1;
        }
    }
}

__global__ __launch_bounds__(256) void k2(
    const float* __restrict__ op_w, const float* __restrict__ op_b,
    const float* __restrict__ ln2_g, const float* __restrict__ ln2_b,
    const float* __restrict__ sa1_w, const float* __restrict__ sa1_b,
    const float* __restrict__ sa2_w, const float* __restrict__ sa2_b)
{
    int tt = threadIdx.x;
    int w = tt >> 5;
    int lane = tt & 31;
    int r = blockIdx.x * 8 + w;

    __shared__ float s_par[8][128];              // params, later reused as cf
    __shared__ __align__(16) float s_tbl[8][TBL_STRIDE];
    __shared__ float w1s[128 * 32];
    __shared__ float b1s[32], w2s[32];

    // stage sa1 weights block-wide
    for (int i = tt; i < 4096; i += 256) w1s[i] = sa1_w[i];
    if (tt < 32) { b1s[tt] = sa1_b[tt]; w2s[tt] = sa2_w[tt]; }

#pragma unroll
    for (int j = 0; j < 4; j++)
        s_par[w][lane + 32 * j] = g_params[r * 128 + lane + 32 * j];
    __syncthreads();

    const float* par = s_par[w];
    float* T = s_tbl[w];

    // ---- phase A: distribute coefficient computation across lanes ----
    if (lane < 24) {
        int a = lane / 6, i = lane % 6;
        const float* base = par + (a >> 1) * 60 + (a & 1) * 30;
        float sa, ca; __sincosf(0.5f * base[3 * i],     &sa, &ca);
        float sb, cb; __sincosf(0.5f * base[3 * i + 1], &sb, &cb);
        float sg, cg; __sincosf(0.5f * base[3 * i + 2], &sg, &cg);
        float ur = cb * ca, ui = sb * sa;
        float wr = sb * ca, wi = -cb * sa;
        T[4 * lane + 0] = cg * ur + sg * ui;   // Pr
        T[4 * lane + 1] = cg * ui - sg * ur;   // Pi
        T[4 * lane + 2] = sg * wi - cg * wr;   // Qr
        T[4 * lane + 3] = cg * wi + sg * wr;   // Qi
    }
    for (int gg = lane; gg < 48; gg += 32) {
        int a = gg / 12, j = gg % 12;
        const float* base = par + (a >> 1) * 60 + (a & 1) * 30;
        float s, c; __sincosf(0.5f * base[18 + j], &s, &c);
        T[96 + 2 * gg] = c; T[97 + 2 * gg] = s;
    }
    if (lane < 6) {
        float s, c; __sincosf(0.5f * par[120 + lane], &s, &c);
        T[192 + 2 * lane] = c; T[193 + 2 * lane] = s;
    }
    __syncwarp();

    // ---- initial product state after per-qubit RY on |0> ----
    float ar0, ai0 = 0.f, ar1, ai1 = 0.f;
    {
        float a0 = 1.f, a1 = 1.f;
#pragma unroll
        for (int i = 0; i < 5; i++) {
            float c = T[192 + 2 * i], s = T[193 + 2 * i];
            float f = ((lane >> (4 - i)) & 1) ? s : c;
            a0 *= f; a1 *= f;
        }
        ar0 = a0 * T[202]; ar1 = a1 * T[203];
    }

    // ---- 4 ansatz applications from the table ----
#pragma unroll
    for (int a = 0; a < 4; a++) {
        const float* F = T + a * 24;
        const float* C = T + 96 + a * 24;
#pragma unroll
        for (int i = 0; i < NQ; i++) {
            float4 pq = *reinterpret_cast<const float4*>(&F[4 * i]);
            apply_su2(i, pq.x, pq.y, pq.z, pq.w, lane, ar0, ai0, ar1, ai1);
        }
#pragma unroll
        for (int j = 0; j < 6; j++) {
            float2 cs = *reinterpret_cast<const float2*>(&C[2 * j]);
            apply_crx(j, (j + 1) % NQ, cs.x, cs.y, lane, ar0, ai0, ar1, ai1);
        }
#pragma unroll
        for (int j = 6; j < 12; j++) {
            float2 cs = *reinterpret_cast<const float2*>(&C[2 * j]);
            int i = 11 - j;
            apply_crx(i, (i + NQ - 1) % NQ, cs.x, cs.y, lane, ar0, ai0, ar1, ai1);
        }
    }

    // ---- measurements ----
    float qv[18];
#pragma unroll
    for (int i = 0; i < NQ; i++) {
        float cr, ci, z;
        float n0 = ar0 * ar0 + ai0 * ai0;
        float n1 = ar1 * ar1 + ai1 * ai1;
        if (i == 5) {
            cr = ar0 * ar1 + ai0 * ai1;
            ci = ar0 * ai1 - ai0 * ar1;
            z  = n0 - n1;
        } else {
            int m = 1 << (4 - i);
            float br0 = __shfl_xor_sync(0xffffffffu, ar0, m), bi0 = __shfl_xor_sync(0xffffffffu, ai0, m);
            float br1 = __shfl_xor_sync(0xffffffffu, ar1, m), bi1 = __shfl_xor_sync(0xffffffffu, ai1, m);
            if (((lane >> (4 - i)) & 1) == 0) {
                cr = ar0 * br0 + ai0 * bi0 + ar1 * br1 + ai1 * bi1;
                ci = ar0 * bi0 - ai0 * br0 + ar1 * bi1 - ai1 * br1;
                z  = n0 + n1;
            } else {
                cr = 0.f; ci = 0.f; z = -(n0 + n1);
            }
        }
#pragma unroll
        for (int o = 16; o; o >>= 1) {
            cr += __shfl_xor_sync(0xffffffffu, cr, o);
            ci += __shfl_xor_sync(0xffffffffu, ci, o);
            z  += __shfl_xor_sync(0xffffffffu, z, o);
        }
        qv[i] = 2.f * cr; qv[6 + i] = 2.f * ci; qv[12 + i] = z;
    }

    // ---- op projection + LN + SiLU ----
    float acc[4];
#pragma unroll
    for (int j = 0; j < 4; j++) {
        int d = lane + 32 * j;
        float a = op_b[d];
#pragma unroll
        for (int k = 0; k < 18; k++) a = fmaf(qv[k], __ldg(&op_w[k * 128 + d]), a);
        acc[j] = a;
    }
    float sum = acc[0] + acc[1] + acc[2] + acc[3];
#pragma unroll
    for (int o = 16; o; o >>= 1) sum += __shfl_xor_sync(0xffffffffu, sum, o);
    float mean = sum * (1.f / 128.f);
    float vs = 0.f;
#pragma unroll
    for (int j = 0; j < 4; j++) { float d0 = acc[j] - mean; vs = fmaf(d0, d0, vs); }
#pragma unroll
    for (int o = 16; o; o >>= 1) vs += __shfl_xor_sync(0xffffffffu, vs, o);
    float rstd = rsqrtf(vs * (1.f / 128.f) + 1e-5f);

    // cf values: write to global AND into s_par row (params dead now)
    float* cfrow = s_par[w];
#pragma unroll
    for (int j = 0; j < 4; j++) {
        int d = lane + 32 * j;
        float xv = (acc[j] - mean) * rstd * ln2_g[d] + ln2_b[d];
        float cf = xv / (1.f + __expf(-xv));
        g_cf[r * 128 + d] = cf;
        cfrow[d] = cf;
    }
    __syncwarp();

    // ---- fused sequence-attention score: lane = hidden col ----
    {
        float a = b1s[lane];
#pragma unroll 4
        for (int dd = 0; dd < 128; dd++)
            a = fmaf(cfrow[dd], w1s[dd * 32 + lane], a);
        float v = tanh_fast(a) * w2s[lane];
#pragma unroll
        for (int o = 16; o; o >>= 1) v += __shfl_xor_sync(0xffffffffu, v, o);
        if (lane == 0) g_ss[r] = v + sa2_b[0];
    }
}

// ===========================================================================
// Kernel k3b: per-batch softmax + weighted sum + classifier (512 threads)
// ===========================================================================
__global__ __launch_bounds__(512) void k3b(
    const float* __restrict__ cl1_w, const float* __restrict__ cl1_b,
    const float* __restrict__ cl2_w, const float* __restrict__ cl2_b,
    float* __restrict__ out)
{
    int b = blockIdx.x;
    int t = threadIdx.x, lane = t & 31, w = t >> 5;
    const float* cf = g_cf + (size_t)b * NCHUNK * DM;

    __shared__ float red[8];
    __shared__ float sw_s[NCHUNK];
    __shared__ float part[4][DM];
    __shared__ float rep_s[DM];
    __shared__ float u_s[64];

    float v = 0.f, e = 0.f;
    if (t < 128) {
        v = g_ss[b * NCHUNK + t];
        float m = v;
#pragma unroll
        for (int o = 16; o; o >>= 1) m = fmaxf(m, __shfl_xor_sync(0xffffffffu, m, o));
        if (lane == 0) red[w] = m;
    }
    __syncthreads();
    float mg = fmaxf(fmaxf(red[0], red[1]), fmaxf(red[2], red[3]));
    if (t < 128) {
        e = __expf(v - mg);
        float sl = e;
#pragma unroll
        for (int o = 16; o; o >>= 1) sl += __shfl_xor_sync(0xffffffffu, sl, o);
        if (lane == 0) red[4 + w] = sl;
    }
    __syncthreads();
    float tot = red[4] + red[5] + red[6] + red[7];
    if (t < 128) sw_s[t] = e / tot;
    __syncthreads();

    {
        int d = t & 127, q = t >> 7;
        float acc = 0.f;
#pragma unroll 4
        for (int n = q * 32; n < q * 32 + 32; n++)
            acc = fmaf(sw_s[n], __ldg(&cf[n * DM + d]), acc);
        part[q][d] = acc;
    }
    __syncthreads();
    if (t < 128) rep_s[t] = part[0][t] + part[1][t] + part[2][t] + part[3][t];
    __syncthreads();

    if (t < 64) {
        float a = cl1_b[t];
#pragma unroll 4
        for (int d = 0; d < DM; d++) a = fmaf(rep_s[d], __ldg(&cl1_w[d * 64 + t]), a);
        u_s[t] = a / (1.f + __expf(-a));
    }
    __syncthreads();
    if (t < 2) {
        float a = cl2_b[t];
#pragma unroll 4
        for (int j = 0; j < 64; j++) a = fmaf(u_s[j], __ldg(&cl2_w[j * 2 + t]), a);
        out[b * 2 + t] = a;
    }
}

// ===========================================================================
extern "C" void kernel_launch(void* const* d_in, const int* in_sizes, int n_in,
                              void* d_out, int out_size)
{
    const float* x      = (const float*)d_in[0];
    const float* conv_w = (const float*)d_in[1];
    const float* conv_b = (const float*)d_in[2];
    const float* ln1_g  = (const float*)d_in[3];
    const float* ln1_b  = (const float*)d_in[4];
    const float* ca1_w  = (const float*)d_in[5];
    const float* ca1_b  = (const float*)d_in[6];
    const float* ca2_w  = (const float*)d_in[7];
    const float* ca2_b  = (const float*)d_in[8];
    const float* pp_w   = (const float*)d_in[9];
    const float* pp_b   = (const float*)d_in[10];
    const float* ep_w   = (const float*)d_in[11];
    const float* ep_b   = (const float*)d_in[12];
    const float* op_w   = (const float*)d_in[13];
    const float* op_b   = (const float*)d_in[14];
    const float* ln2_g  = (const float*)d_in[15];
    const float* ln2_b  = (const float*)d_in[16];
    const float* sa1_w  = (const float*)d_in[17];
    const float* sa1_b  = (const float*)d_in[18];
    const float* sa2_w  = (const float*)d_in[19];
    const float* sa2_b  = (const float*)d_in[20];
    const float* cl1_w  = (const float*)d_in[21];
    const float* cl1_b  = (const float*)d_in[22];
    const float* cl2_w  = (const float*)d_in[23];
    const float* cl2_b  = (const float*)d_in[24];
    float* out = (float*)d_out;

    cudaFuncSetAttribute(k1, cudaFuncAttributeMaxDynamicSharedMemorySize, (int)sizeof(K1Smem));
    cudaFuncSetAttribute(k_pp, cudaFuncAttributeMaxDynamicSharedMemorySize, (int)sizeof(KPSmem));

    k1<<<BATCH * 16, 256, sizeof(K1Smem)>>>(x, conv_w, conv_b, ln1_g, ln1_b,
                                            ca1_w, ca1_b, ca2_w, ca2_b, ep_w, ep_b);
    k_pp<<<NROWS / 64, 256, sizeof(KPSmem)>>>(pp_w, pp_b);
    k2<<<NROWS / 8, 256>>>(op_w, op_b, ln2_g, ln2_b, sa1_w, sa1_b, sa2_w, sa2_b);
    k3b<<<BATCH, 512>>>(cl1_w, cl1_b, cl2_w, cl2_b, out);
}

// round 7
// speedup vs baseline: 2.0777x; 1.0790x over previous
#include <cuda_runtime.h>
#include <math_constants.h>

#define NQ 6
#define DM 128
#define SEQ 2048
#define CHUNK 16
#define BATCH 128
#define NCHUNK (SEQ / CHUNK)      // 128
#define NROWS (BATCH * NCHUNK)    // 16384

typedef unsigned long long ull;

// Scratch (device globals; no allocation allowed)
__device__ float g_params[NROWS * 128];  // per row: fp[60], mp[60], ang[6], pad[2]
__device__ float g_summ[NROWS * 128];    // per row: summ (DM)
__device__ float g_cf[NROWS * 128];      // per row: chunk feature (DM)
__device__ float g_ss[NROWS];            // per row: sequence-attention score

__device__ __forceinline__ float tanh_fast(float x) {
    float y; asm("tanh.approx.f32 %0, %1;" : "=f"(y) : "f"(x)); return y;
}

// ---- packed fp32x2 helpers (Blackwell FFMA2 path; exact fp32 per half) ----
__device__ __forceinline__ ull pack2(float lo, float hi) {
    ull r; asm("mov.b64 %0, {%1, %2};" : "=l"(r) : "f"(lo), "f"(hi)); return r;
}
__device__ __forceinline__ void fma2(ull& d, ull a, ull b) {
    asm("fma.rn.f32x2 %0, %1, %2, %3;" : "=l"(d) : "l"(a), "l"(b), "l"(d));
}
__device__ __forceinline__ float2 unpack2(ull v) {
    float2 f; asm("mov.b64 {%0, %1}, %2;" : "=f"(f.x), "=f"(f.y) : "l"(v)); return f;
}

// ===========================================================================
// Kernel 1: conv1d + (folded LN) + chunk attention + ep projection
// one block = 8 chunks (128 seq positions) of one batch row; 256 threads
// LN is never materialized: folded into score GEMM and weighted sum.
// ===========================================================================
struct K1Smem {
    float sx[4][132];
    float ht[128 * 130];     // RAW conv output, d-major
    float w1[128 * 32];      // ca1_w * ln1_g  (wg1)
    float cw[128 * 13];
    float lng[128], lnb[128];
    float b1[32], w2[32];
    float scp[4 * 128];      // reused: stats partials, then score partials
    float redw[256], redb[256];
    float cw1[32], cb1[32];
    float wgt[128];          // a[p] = softmax_w[p] * rv[p]
    float chC[16];           // per-chunk Sum_p wgt*rv*m
    float mv[128], rv[128];
    float summ[8 * 128];
    float epw[768];
    float epb[8];
};

__global__ __launch_bounds__(256) void k1(
    const float* __restrict__ x, const float* __restrict__ conv_w, const float* __restrict__ conv_b,
    const float* __restrict__ ln1_g, const float* __restrict__ ln1_b,
    const float* __restrict__ ca1_w, const float* __restrict__ ca1_b,
    const float* __restrict__ ca2_w, const float* __restrict__ ca2_b,
    const float* __restrict__ ep_w, const float* __restrict__ ep_b)
{
    extern __shared__ char smem_raw[];
    K1Smem& S = *reinterpret_cast<K1Smem*>(smem_raw);

    const int bid = blockIdx.x;
    const int b = bid >> 4;
    const int g = bid & 15;
    const int s_base = g * 128;
    const int t = threadIdx.x;

    // ---- stage ----
    if (t < 128) { S.lng[t] = ln1_g[t]; S.lnb[t] = ln1_b[t]; }
    for (int i = t; i < 4096; i += 256) S.w1[i] = ca1_w[i] * __ldg(&ln1_g[i >> 5]);
    for (int i = t; i < 1536; i += 256) S.cw[(i / 12) * 13 + (i % 12)] = conv_w[i];
    if (t < 32) { S.b1[t] = ca1_b[t]; S.w2[t] = ca2_w[t]; }
    for (int i = t; i < 768; i += 256) S.epw[i] = ep_w[i];
    if (t < 6) S.epb[t] = ep_b[t];
    for (int i = t; i < 4 * 130; i += 256) {
        int c = i / 130, k = i % 130;
        int s = s_base - 1 + k;
        float v = 0.f;
        if (s >= 0 && s < SEQ) v = x[(b * 4 + c) * SEQ + s];
        S.sx[c][k] = v;
    }
    __syncthreads();

    const int d = t & 127;
    const int half = t >> 7;

    // ---- cw1/cb1 partials (8 segs x 32 cols) ----
    {
        int j = t & 31, seg = t >> 5;
        float pw = 0.f, pb = 0.f;
#pragma unroll 4
        for (int dd = seg * 16; dd < seg * 16 + 16; dd++) {
            pw += S.w1[dd * 32 + j];
            pb = fmaf(__ldg(&ca1_w[dd * 32 + j]), S.lnb[dd], pb);
        }
        S.redw[seg * 32 + j] = pw;
        S.redb[seg * 32 + j] = pb;
    }

    // ---- conv (packed 2 positions per step), RAW output ----
    {
        const int p0c = half * 64;
        ull wp[12];
#pragma unroll
        for (int k = 0; k < 12; k++) { float wv = S.cw[d * 13 + k]; wp[k] = pack2(wv, wv); }
        float bv = conv_b[d];
        ull bias2 = pack2(bv, bv);
        float xs0[4], xs1[4];
#pragma unroll
        for (int c = 0; c < 4; c++) { xs0[c] = S.sx[c][p0c]; xs1[c] = S.sx[c][p0c + 1]; }
#pragma unroll 4
        for (int p = p0c; p < p0c + 64; p += 2) {
            ull a2 = bias2;
#pragma unroll
            for (int c = 0; c < 4; c++) {
                float x2 = S.sx[c][p + 2], x3 = S.sx[c][p + 3];
                fma2(a2, pack2(xs0[c], xs1[c]), wp[c * 3 + 0]);
                fma2(a2, pack2(xs1[c], x2),     wp[c * 3 + 1]);
                fma2(a2, pack2(x2, x3),         wp[c * 3 + 2]);
                xs0[c] = x2; xs1[c] = x3;
            }
            float2 f = unpack2(a2);
            S.ht[d * 130 + p] = f.x;
            S.ht[d * 130 + p + 1] = f.y;
        }
    }
    __syncthreads();

    // ---- LN stats partials: thread = (pos, dim-half of 64) ----
    {
        int pos = t & 127;
        float s = 0.f, ss = 0.f;
#pragma unroll 4
        for (int dd = half * 64; dd < half * 64 + 64; dd++) {
            float v = S.ht[dd * 130 + pos];
            s += v; ss = fmaf(v, v, ss);
        }
        S.scp[t] = s; S.scp[256 + t] = ss;
    }
    __syncthreads();
    // combine stats (t<128) and finalize cw1/cb1 (t in [128,160))
    if (t < 128) {
        float s = S.scp[t] + S.scp[128 + t];
        float ss = S.scp[256 + t] + S.scp[384 + t];
        float m = s * (1.f / 128.f);
        float var = ss * (1.f / 128.f) - m * m;
        S.mv[t] = m; S.rv[t] = rsqrtf(var + 1e-5f);
    } else if (t < 160) {
        int j = t - 128;
        float sw = 0.f, sb = 0.f;
#pragma unroll
        for (int seg = 0; seg < 8; seg++) {
            sw += S.redw[seg * 32 + j];
            sb += S.redb[seg * 32 + j];
        }
        S.cw1[j] = sw; S.cb1[j] = sb;
    }
    __syncthreads();

    // ---- scores on RAW h with folded LN affine ----
    {
        const int pp = t & 63;
        const int p0 = 2 * pp;
        const int jq = t >> 6;
        const int j0 = 8 * jq;
        ull acc2[2][4];
#pragma unroll
        for (int r = 0; r < 2; r++)
#pragma unroll
            for (int c = 0; c < 4; c++) acc2[r][c] = 0ull;
        for (int dd = 0; dd < 128; dd++) {
            float2 h2 = *reinterpret_cast<const float2*>(&S.ht[dd * 130 + p0]);
            ull hx = pack2(h2.x, h2.x), hy = pack2(h2.y, h2.y);
            ulonglong2 wpa = *reinterpret_cast<const ulonglong2*>(&S.w1[dd * 32 + j0]);
            ulonglong2 wpb = *reinterpret_cast<const ulonglong2*>(&S.w1[dd * 32 + j0 + 4]);
            fma2(acc2[0][0], hx, wpa.x); fma2(acc2[0][1], hx, wpa.y);
            fma2(acc2[0][2], hx, wpb.x); fma2(acc2[0][3], hx, wpb.y);
            fma2(acc2[1][0], hy, wpa.x); fma2(acc2[1][1], hy, wpa.y);
            fma2(acc2[1][2], hy, wpb.x); fma2(acc2[1][3], hy, wpb.y);
        }
#pragma unroll
        for (int r = 0; r < 2; r++) {
            float rvp = S.rv[p0 + r];
            float rm = rvp * S.mv[p0 + r];
            float sp = 0.f;
#pragma unroll
            for (int c = 0; c < 4; c++) {
                float2 f = unpack2(acc2[r][c]);
                int j = j0 + 2 * c;
                float v0 = rvp * f.x - rm * S.cw1[j]     + S.cb1[j]     + S.b1[j];
                float v1 = rvp * f.y - rm * S.cw1[j + 1] + S.cb1[j + 1] + S.b1[j + 1];
                sp = fmaf(tanh_fast(v0), S.w2[j],     sp);
                sp = fmaf(tanh_fast(v1), S.w2[j + 1], sp);
            }
            S.scp[jq * 128 + p0 + r] = sp;
        }
    }
    __syncthreads();

    // ---- combine + softmax per chunk; also a[p]=wgt*rv, chC[c]=Sum wgt*rv*m ----
    if (t < 128) {
        float v = S.scp[t] + S.scp[128 + t] + S.scp[256 + t] + S.scp[384 + t] + ca2_b[0];
        float m = v;
#pragma unroll
        for (int o = 8; o; o >>= 1) m = fmaxf(m, __shfl_xor_sync(0xffffffffu, m, o, 16));
        float e = __expf(v - m);
        float sm = e;
#pragma unroll
        for (int o = 8; o; o >>= 1) sm += __shfl_xor_sync(0xffffffffu, sm, o, 16);
        float wv = e / sm;
        float aval = wv * S.rv[t];
        S.wgt[t] = aval;
        float cc = aval * S.mv[t];
#pragma unroll
        for (int o = 8; o; o >>= 1) cc += __shfl_xor_sync(0xffffffffu, cc, o, 16);
        if ((t & 15) == 0) S.chC[t >> 4] = cc;
    }
    __syncthreads();

    // ---- weighted sums on RAW h with folded LN ----
    {
        float gd = S.lng[d], bd = S.lnb[d];
        for (int c = 4 * half; c < 4 * half + 4; c++) {
            float a = 0.f;
#pragma unroll
            for (int p = 0; p < 16; p++)
                a = fmaf(S.wgt[c * 16 + p], S.ht[d * 130 + c * 16 + p], a);
            float sv = fmaf(gd, a - S.chC[c], bd);
            S.summ[c * 128 + d] = sv;
            g_summ[(b * 128 + g * 8 + c) * 128 + d] = sv;
        }
    }
    __syncthreads();

    // ---- ep projection -> angles (precise tanh: feeds quantum circuit) ----
    if (t < 48) {
        int r = t / 6, j = t % 6;
        float a = S.epb[j];
        for (int dd = 0; dd < 128; dd++)
            a = fmaf(S.summ[r * 128 + dd], S.epw[dd * 6 + j], a);
        g_params[(b * 128 + g * 8 + r) * 128 + 120 + j] =
            tanhf(a) * 3.14159265358979323846f;
    }
}

// ===========================================================================
// Kernel k_pp: pp projection GEMM  (16384 x 128) @ (128 x 120), f32x2 packed
// ===========================================================================
struct KPSmem {
    float w[128 * 128];
    float s[64 * 129];
};

__global__ __launch_bounds__(256) void k_pp(
    const float* __restrict__ pp_w, const float* __restrict__ pp_b)
{
    extern __shared__ char smem_raw[];
    KPSmem& S = *reinterpret_cast<KPSmem*>(smem_raw);
    const int t = threadIdx.x;
    const int r0 = blockIdx.x * 64;

    for (int i = t; i < 128 * 128; i += 256) S.w[i] = 0.f;
    __syncthreads();
    for (int i = t; i < 128 * 120; i += 256) {
        int dd = i / 120, j = i % 120;
        S.w[dd * 128 + j] = pp_w[i];
    }
    for (int i = t; i < 64 * 128; i += 256) {
        int r = i >> 7, c = i & 127;
        S.s[r * 129 + c] = g_summ[(r0 + r) * 128 + c];
    }
    __syncthreads();

    const int tx = t & 15;
    const int ty = t >> 4;
    ull acc2[4][4];
#pragma unroll
    for (int i = 0; i < 4; i++)
#pragma unroll
        for (int c = 0; c < 4; c++) acc2[i][c] = 0ull;

    for (int dd = 0; dd < 128; dd++) {
        ulonglong2 wpa = *reinterpret_cast<const ulonglong2*>(&S.w[dd * 128 + 8 * tx]);
        ulonglong2 wpb = *reinterpret_cast<const ulonglong2*>(&S.w[dd * 128 + 8 * tx + 4]);
        ull sv2[4];
#pragma unroll
        for (int i = 0; i < 4; i++) {
            float sv = S.s[(4 * ty + i) * 129 + dd];
            sv2[i] = pack2(sv, sv);
        }
#pragma unroll
        for (int i = 0; i < 4; i++) {
            fma2(acc2[i][0], sv2[i], wpa.x);
            fma2(acc2[i][1], sv2[i], wpa.y);
            fma2(acc2[i][2], sv2[i], wpb.x);
            fma2(acc2[i][3], sv2[i], wpb.y);
        }
    }
#pragma unroll
    for (int i = 0; i < 4; i++) {
        int gr = r0 + 4 * ty + i;
#pragma unroll
        for (int c = 0; c < 4; c++) {
            float2 f = unpack2(acc2[i][c]);
            int j = 8 * tx + 2 * c;
            if (j < 120)     g_params[gr * 128 + j]     = f.x + pp_b[j];
            if (j + 1 < 120) g_params[gr * 128 + j + 1] = f.y + pp_b[j + 1];
        }
    }
}

// ===========================================================================
// Kernel 2: quantum circuit (warp per row) + op projection + LN + SiLU
//           + fused sequence-attention score
// ===========================================================================
#define TBL_STRIDE 208

__device__ __forceinline__ void apply_su2(int q, float Pr, float Pi, float Qr, float Qi,
    int lane, float& ar0, float& ai0, float& ar1, float& ai1)
{
    if (q == 5) {
        float n0r =  Pr * ar0 - Pi * ai0 + Qr * ar1 - Qi * ai1;
        float n0i =  Pr * ai0 + Pi * ar0 + Qr * ai1 + Qi * ar1;
        float n1r = -Qr * ar0 - Qi * ai0 + Pr * ar1 + Pi * ai1;
        float n1i = -Qr * ai0 + Qi * ar0 + Pr * ai1 - Pi * ar1;
        ar0 = n0r; ai0 = n0i; ar1 = n1r; ai1 = n1i;
    } else {
        int m = 1 << (4 - q);
        float br0 = __shfl_xor_sync(0xffffffffu, ar0, m), bi0 = __shfl_xor_sync(0xffffffffu, ai0, m);
        float br1 = __shfl_xor_sync(0xffffffffu, ar1, m), bi1 = __shfl_xor_sync(0xffffffffu, ai1, m);
        int bit = (lane >> (4 - q)) & 1;
        float lPi = bit ? -Pi : Pi;
        float lQr = bit ? -Qr : Qr;
        float n0r = Pr * ar0 - lPi * ai0 + lQr * br0 - Qi * bi0;
        float n0i = Pr * ai0 + lPi * ar0 + lQr * bi0 + Qi * br0;
        float n1r = Pr * ar1 - lPi * ai1 + lQr * br1 - Qi * bi1;
        float n1i = Pr * ai1 + lPi * ar1 + lQr * bi1 + Qi * br1;
        ar0 = n0r; ai0 = n0i; ar1 = n1r; ai1 = n1i;
    }
}

__device__ __forceinline__ void apply_crx(int cq, int tq, float c, float s,
    int lane, float& ar0, float& ai0, float& ar1, float& ai1)
{
    if (cq == 5) {
        int m = 1 << (4 - tq);
        float br1 = __shfl_xor_sync(0xffffffffu, ar1, m), bi1 = __shfl_xor_sync(0xffffffffu, ai1, m);
        ar1 = c * ar1 + s * bi1; ai1 = c * ai1 - s * br1;
    } else if (tq == 5) {
        if ((lane >> (4 - cq)) & 1) {
            float nr0 = c * ar0 + s * ai1, ni0 = c * ai0 - s * ar1;
            float nr1 = c * ar1 + s * ai0, ni1 = c * ai1 - s * ar0;
            ar0 = nr0; ai0 = ni0; ar1 = nr1; ai1 = ni1;
        }
    } else {
        int m = 1 << (4 - tq);
        float br0 = __shfl_xor_sync(0xffffffffu, ar0, m), bi0 = __shfl_xor_sync(0xffffffffu, ai0, m);
        float br1 = __shfl_xor_sync(0xffffffffu, ar1, m), bi1 = __shfl_xor_sync(0xffffffffu, ai1, m);
        if ((lane >> (4 - cq)) & 1) {
            ar0 = c * ar0 + s * bi0; ai0 = c * ai0 - s * br0;
            ar1 = c * ar1 + s * bi1; ai1 = c * ai1 - s * br1;
        }
    }
}

__global__ __launch_bounds__(256) void k2(
    const float* __restrict__ op_w, const float* __restrict__ op_b,
    const float* __restrict__ ln2_g, const float* __restrict__ ln2_b,
    const float* __restrict__ sa1_w, const float* __restrict__ sa1_b,
    const float* __restrict__ sa2_w, const float* __restrict__ sa2_b)
{
    int tt = threadIdx.x;
    int w = tt >> 5;
    int lane = tt & 31;
    int r = blockIdx.x * 8 + w;

    __shared__ float s_par[8][128];              // params, later reused as cf
    __shared__ __align__(16) float s_tbl[8][TBL_STRIDE];
    __shared__ float w1s[128 * 32];
    __shared__ float b1s[32], w2s[32];

    for (int i = tt; i < 4096; i += 256) w1s[i] = sa1_w[i];
    if (tt < 32) { b1s[tt] = sa1_b[tt]; w2s[tt] = sa2_w[tt]; }

#pragma unroll
    for (int j = 0; j < 4; j++)
        s_par[w][lane + 32 * j] = g_params[r * 128 + lane + 32 * j];
    __syncthreads();

    const float* par = s_par[w];
    float* T = s_tbl[w];

    if (lane < 24) {
        int a = lane / 6, i = lane % 6;
        const float* base = par + (a >> 1) * 60 + (a & 1) * 30;
        float sa, ca; __sincosf(0.5f * base[3 * i],     &sa, &ca);
        float sb, cb; __sincosf(0.5f * base[3 * i + 1], &sb, &cb);
        float sg, cg; __sincosf(0.5f * base[3 * i + 2], &sg, &cg);
        float ur = cb * ca, ui = sb * sa;
        float wr = sb * ca, wi = -cb * sa;
        T[4 * lane + 0] = cg * ur + sg * ui;
        T[4 * lane + 1] = cg * ui - sg * ur;
        T[4 * lane + 2] = sg * wi - cg * wr;
        T[4 * lane + 3] = cg * wi + sg * wr;
    }
    for (int gg = lane; gg < 48; gg += 32) {
        int a = gg / 12, j = gg % 12;
        const float* base = par + (a >> 1) * 60 + (a & 1) * 30;
        float s, c; __sincosf(0.5f * base[18 + j], &s, &c);
        T[96 + 2 * gg] = c; T[97 + 2 * gg] = s;
    }
    if (lane < 6) {
        float s, c; __sincosf(0.5f * par[120 + lane], &s, &c);
        T[192 + 2 * lane] = c; T[193 + 2 * lane] = s;
    }
    __syncwarp();

    float ar0, ai0 = 0.f, ar1, ai1 = 0.f;
    {
        float a0 = 1.f, a1 = 1.f;
#pragma unroll
        for (int i = 0; i < 5; i++) {
            float c = T[192 + 2 * i], s = T[193 + 2 * i];
            float f = ((lane >> (4 - i)) & 1) ? s : c;
            a0 *= f; a1 *= f;
        }
        ar0 = a0 * T[202]; ar1 = a1 * T[203];
    }

#pragma unroll
    for (int a = 0; a < 4; a++) {
        const float* F = T + a * 24;
        const float* C = T + 96 + a * 24;
#pragma unroll
        for (int i = 0; i < NQ; i++) {
            float4 pq = *reinterpret_cast<const float4*>(&F[4 * i]);
            apply_su2(i, pq.x, pq.y, pq.z, pq.w, lane, ar0, ai0, ar1, ai1);
        }
#pragma unroll
        for (int j = 0; j < 6; j++) {
            float2 cs = *reinterpret_cast<const float2*>(&C[2 * j]);
            apply_crx(j, (j + 1) % NQ, cs.x, cs.y, lane, ar0, ai0, ar1, ai1);
        }
#pragma unroll
        for (int j = 6; j < 12; j++) {
            float2 cs = *reinterpret_cast<const float2*>(&C[2 * j]);
            int i = 11 - j;
            apply_crx(i, (i + NQ - 1) % NQ, cs.x, cs.y, lane, ar0, ai0, ar1, ai1);
        }
    }

    float qv[18];
#pragma unroll
    for (int i = 0; i < NQ; i++) {
        float cr, ci, z;
        float n0 = ar0 * ar0 + ai0 * ai0;
        float n1 = ar1 * ar1 + ai1 * ai1;
        if (i == 5) {
            cr = ar0 * ar1 + ai0 * ai1;
            ci = ar0 * ai1 - ai0 * ar1;
            z  = n0 - n1;
        } else {
            int m = 1 << (4 - i);
            float br0 = __shfl_xor_sync(0xffffffffu, ar0, m), bi0 = __shfl_xor_sync(0xffffffffu, ai0, m);
            float br1 = __shfl_xor_sync(0xffffffffu, ar1, m), bi1 = __shfl_xor_sync(0xffffffffu, ai1, m);
            if (((lane >> (4 - i)) & 1) == 0) {
                cr = ar0 * br0 + ai0 * bi0 + ar1 * br1 + ai1 * bi1;
                ci = ar0 * bi0 - ai0 * br0 + ar1 * bi1 - ai1 * br1;
                z  = n0 + n1;
            } else {
                cr = 0.f; ci = 0.f; z = -(n0 + n1);
            }
        }
#pragma unroll
        for (int o = 16; o; o >>= 1) {
            cr += __shfl_xor_sync(0xffffffffu, cr, o);
            ci += __shfl_xor_sync(0xffffffffu, ci, o);
            z  += __shfl_xor_sync(0xffffffffu, z, o);
        }
        qv[i] = 2.f * cr; qv[6 + i] = 2.f * ci; qv[12 + i] = z;
    }

    float acc[4];
#pragma unroll
    for (int j = 0; j < 4; j++) {
        int d = lane + 32 * j;
        float a = op_b[d];
#pragma unroll
        for (int k = 0; k < 18; k++) a = fmaf(qv[k], __ldg(&op_w[k * 128 + d]), a);
        acc[j] = a;
    }
    float sum = acc[0] + acc[1] + acc[2] + acc[3];
#pragma unroll
    for (int o = 16; o; o >>= 1) sum += __shfl_xor_sync(0xffffffffu, sum, o);
    float mean = sum * (1.f / 128.f);
    float vs = 0.f;
#pragma unroll
    for (int j = 0; j < 4; j++) { float d0 = acc[j] - mean; vs = fmaf(d0, d0, vs); }
#pragma unroll
    for (int o = 16; o; o >>= 1) vs += __shfl_xor_sync(0xffffffffu, vs, o);
    float rstd = rsqrtf(vs * (1.f / 128.f) + 1e-5f);

    float* cfrow = s_par[w];
#pragma unroll
    for (int j = 0; j < 4; j++) {
        int d = lane + 32 * j;
        float xv = (acc[j] - mean) * rstd * ln2_g[d] + ln2_b[d];
        float cf = xv / (1.f + __expf(-xv));
        g_cf[r * 128 + d] = cf;
        cfrow[d] = cf;
    }
    __syncwarp();

    {
        float a = b1s[lane];
#pragma unroll 4
        for (int dd = 0; dd < 128; dd++)
            a = fmaf(cfrow[dd], w1s[dd * 32 + lane], a);
        float v = tanh_fast(a) * w2s[lane];
#pragma unroll
        for (int o = 16; o; o >>= 1) v += __shfl_xor_sync(0xffffffffu, v, o);
        if (lane == 0) g_ss[r] = v + sa2_b[0];
    }
}

// ===========================================================================
// Kernel k3b: per-batch softmax + weighted sum (float4) + classifier
// ===========================================================================
__global__ __launch_bounds__(512) void k3b(
    const float* __restrict__ cl1_w, const float* __restrict__ cl1_b,
    const float* __restrict__ cl2_w, const float* __restrict__ cl2_b,
    float* __restrict__ out)
{
    int b = blockIdx.x;
    int t = threadIdx.x, lane = t & 31, w = t >> 5;
    const float4* cf4 = reinterpret_cast<const float4*>(g_cf + (size_t)b * NCHUNK * DM);

    __shared__ float red[8];
    __shared__ float sw_s[NCHUNK];
    __shared__ float4 part4[16][32];
    __shared__ float rep_s[DM];
    __shared__ float u_s[64];

    float v = 0.f, e = 0.f;
    if (t < 128) {
        v = g_ss[b * NCHUNK + t];
        float m = v;
#pragma unroll
        for (int o = 16; o; o >>= 1) m = fmaxf(m, __shfl_xor_sync(0xffffffffu, m, o));
        if (lane == 0) red[w] = m;
    }
    __syncthreads();
    float mg = fmaxf(fmaxf(red[0], red[1]), fmaxf(red[2], red[3]));
    if (t < 128) {
        e = __expf(v - mg);
        float sl = e;
#pragma unroll
        for (int o = 16; o; o >>= 1) sl += __shfl_xor_sync(0xffffffffu, sl, o);
        if (lane == 0) red[4 + w] = sl;
    }
    __syncthreads();
    float tot = red[4] + red[5] + red[6] + red[7];
    if (t < 128) sw_s[t] = e / tot;
    __syncthreads();

    // weighted sum: thread = (float4 channel d4, chunk-group q of 8)
    {
        int d4 = t & 31, q = t >> 5;
        float4 acc = make_float4(0.f, 0.f, 0.f, 0.f);
#pragma unroll
        for (int n = q * 8; n < q * 8 + 8; n++) {
            float swv = sw_s[n];
            float4 cv = __ldg(&cf4[n * 32 + d4]);
            acc.x = fmaf(swv, cv.x, acc.x);
            acc.y = fmaf(swv, cv.y, acc.y);
            acc.z = fmaf(swv, cv.z, acc.z);
            acc.w = fmaf(swv, cv.w, acc.w);
        }
        part4[q][d4] = acc;
    }
    __syncthreads();
    if (t < 32) {
        float4 r = part4[0][t];
#pragma unroll
        for (int q = 1; q < 16; q++) {
            float4 p = part4[q][t];
            r.x += p.x; r.y += p.y; r.z += p.z; r.w += p.w;
        }
        reinterpret_cast<float4*>(rep_s)[t] = r;
    }
    __syncthreads();

    if (t < 64) {
        float a = cl1_b[t];
#pragma unroll 4
        for (int d = 0; d < DM; d++) a = fmaf(rep_s[d], __ldg(&cl1_w[d * 64 + t]), a);
        u_s[t] = a / (1.f + __expf(-a));
    }
    __syncthreads();
    if (t < 2) {
        float a = cl2_b[t];
#pragma unroll 4
        for (int j = 0; j < 64; j++) a = fmaf(u_s[j], __ldg(&cl2_w[j * 2 + t]), a);
        out[b * 2 + t] = a;
    }
}

// ===========================================================================
extern "C" void kernel_launch(void* const* d_in, const int* in_sizes, int n_in,
                              void* d_out, int out_size)
{
    const float* x      = (const float*)d_in[0];
    const float* conv_w = (const float*)d_in[1];
    const float* conv_b = (const float*)d_in[2];
    const float* ln1_g  = (const float*)d_in[3];
    const float* ln1_b  = (const float*)d_in[4];
    const float* ca1_w  = (const float*)d_in[5];
    const float* ca1_b  = (const float*)d_in[6];
    const float* ca2_w  = (const float*)d_in[7];
    const float* ca2_b  = (const float*)d_in[8];
    const float* pp_w   = (const float*)d_in[9];
    const float* pp_b   = (const float*)d_in[10];
    const float* ep_w   = (const float*)d_in[11];
    const float* ep_b   = (const float*)d_in[12];
    const float* op_w   = (const float*)d_in[13];
    const float* op_b   = (const float*)d_in[14];
    const float* ln2_g  = (const float*)d_in[15];
    const float* ln2_b  = (const float*)d_in[16];
    const float* sa1_w  = (const float*)d_in[17];
    const float* sa1_b  = (const float*)d_in[18];
    const float* sa2_w  = (const float*)d_in[19];
    const float* sa2_b  = (const float*)d_in[20];
    const float* cl1_w  = (const float*)d_in[21];
    const float* cl1_b  = (const float*)d_in[22];
    const float* cl2_w  = (const float*)d_in[23];
    const float* cl2_b  = (const float*)d_in[24];
    float* out = (float*)d_out;

    cudaFuncSetAttribute(k1, cudaFuncAttributeMaxDynamicSharedMemorySize, (int)sizeof(K1Smem));
    cudaFuncSetAttribute(k_pp, cudaFuncAttributeMaxDynamicSharedMemorySize, (int)sizeof(KPSmem));

    k1<<<BATCH * 16, 256, sizeof(K1Smem)>>>(x, conv_w, conv_b, ln1_g, ln1_b,
                                            ca1_w, ca1_b, ca2_w, ca2_b, ep_w, ep_b);
    k_pp<<<NROWS / 64, 256, sizeof(KPSmem)>>>(pp_w, pp_b);
    k2<<<NROWS / 8, 256>>>(op_w, op_b, ln2_g, ln2_b, sa1_w, sa1_b, sa2_w, sa2_b);
    k3b<<<BATCH, 512>>>(cl1_w, cl1_b, cl2_w, cl2_b, out);
}

// round 8
// speedup vs baseline: 2.1541x; 1.0368x over previous
#include <cuda_runtime.h>
#include <math_constants.h>

#define NQ 6
#define DM 128
#define SEQ 2048
#define CHUNK 16
#define BATCH 128
#define NCHUNK (SEQ / CHUNK)      // 128
#define NROWS (BATCH * NCHUNK)    // 16384

typedef unsigned long long ull;

// Scratch (device globals; no allocation allowed)
__device__ float g_params[NROWS * 128];  // per row: fp[60], mp[60], ang[6], pad[2]
__device__ float g_summ[NROWS * 128];    // per row: summ (DM)
__device__ float g_cf[NROWS * 128];      // per row: chunk feature (DM)
__device__ float g_ss[NROWS];            // per row: sequence-attention score
__device__ float g_rep[BATCH * DM];      // per batch: attention-pooled rep

__device__ __forceinline__ float tanh_fast(float x) {
    float y; asm("tanh.approx.f32 %0, %1;" : "=f"(y) : "f"(x)); return y;
}

// ---- packed fp32x2 helpers (Blackwell FFMA2 path; exact fp32 per half) ----
__device__ __forceinline__ ull pack2(float lo, float hi) {
    ull r; asm("mov.b64 %0, {%1, %2};" : "=l"(r) : "f"(lo), "f"(hi)); return r;
}
__device__ __forceinline__ void fma2(ull& d, ull a, ull b) {
    asm("fma.rn.f32x2 %0, %1, %2, %3;" : "=l"(d) : "l"(a), "l"(b), "l"(d));
}
__device__ __forceinline__ float2 unpack2(ull v) {
    float2 f; asm("mov.b64 {%0, %1}, %2;" : "=f"(f.x), "=f"(f.y) : "l"(v)); return f;
}

// ===========================================================================
// Kernel 1: conv1d + (folded LN) + chunk attention + ep projection
// one block = 8 chunks (128 seq positions) of one batch row; 256 threads
// ===========================================================================
struct K1Smem {
    float sx[4][132];
    float ht[128 * 130];     // RAW conv output, d-major
    float w1[128 * 32];      // ca1_w * ln1_g
    float cw[128 * 13];
    float lng[128], lnb[128];
    float b1[32], w2[32];
    float scp[4 * 128];      // reused: stats partials, score partials, ep partials
    float redw[256], redb[256];
    float cw1[32], cb1[32];
    float wgt[128];
    float chC[16];
    float mv[128], rv[128];
    float summ[8 * 128];
    float epw[768];
    float epb[8];
};

__global__ __launch_bounds__(256) void k1(
    const float* __restrict__ x, const float* __restrict__ conv_w, const float* __restrict__ conv_b,
    const float* __restrict__ ln1_g, const float* __restrict__ ln1_b,
    const float* __restrict__ ca1_w, const float* __restrict__ ca1_b,
    const float* __restrict__ ca2_w, const float* __restrict__ ca2_b,
    const float* __restrict__ ep_w, const float* __restrict__ ep_b)
{
    extern __shared__ char smem_raw[];
    K1Smem& S = *reinterpret_cast<K1Smem*>(smem_raw);

    const int bid = blockIdx.x;
    const int b = bid >> 4;
    const int g = bid & 15;
    const int s_base = g * 128;
    const int t = threadIdx.x;

    if (t < 128) { S.lng[t] = ln1_g[t]; S.lnb[t] = ln1_b[t]; }
    for (int i = t; i < 4096; i += 256) S.w1[i] = ca1_w[i] * __ldg(&ln1_g[i >> 5]);
    for (int i = t; i < 1536; i += 256) S.cw[(i / 12) * 13 + (i % 12)] = conv_w[i];
    if (t < 32) { S.b1[t] = ca1_b[t]; S.w2[t] = ca2_w[t]; }
    for (int i = t; i < 768; i += 256) S.epw[i] = ep_w[i];
    if (t < 6) S.epb[t] = ep_b[t];
    for (int i = t; i < 4 * 130; i += 256) {
        int c = i / 130, k = i % 130;
        int s = s_base - 1 + k;
        float v = 0.f;
        if (s >= 0 && s < SEQ) v = x[(b * 4 + c) * SEQ + s];
        S.sx[c][k] = v;
    }
    __syncthreads();

    const int d = t & 127;
    const int half = t >> 7;

    // ---- cw1/cb1 partials ----
    {
        int j = t & 31, seg = t >> 5;
        float pw = 0.f, pb = 0.f;
#pragma unroll 4
        for (int dd = seg * 16; dd < seg * 16 + 16; dd++) {
            pw += S.w1[dd * 32 + j];
            pb = fmaf(__ldg(&ca1_w[dd * 32 + j]), S.lnb[dd], pb);
        }
        S.redw[seg * 32 + j] = pw;
        S.redb[seg * 32 + j] = pb;
    }

    // ---- conv (packed 2 positions per step), RAW output ----
    {
        const int p0c = half * 64;
        ull wp[12];
#pragma unroll
        for (int k = 0; k < 12; k++) { float wv = S.cw[d * 13 + k]; wp[k] = pack2(wv, wv); }
        float bv = conv_b[d];
        ull bias2 = pack2(bv, bv);
        float xs0[4], xs1[4];
#pragma unroll
        for (int c = 0; c < 4; c++) { xs0[c] = S.sx[c][p0c]; xs1[c] = S.sx[c][p0c + 1]; }
#pragma unroll 4
        for (int p = p0c; p < p0c + 64; p += 2) {
            ull a2 = bias2;
#pragma unroll
            for (int c = 0; c < 4; c++) {
                float x2 = S.sx[c][p + 2], x3 = S.sx[c][p + 3];
                fma2(a2, pack2(xs0[c], xs1[c]), wp[c * 3 + 0]);
                fma2(a2, pack2(xs1[c], x2),     wp[c * 3 + 1]);
                fma2(a2, pack2(x2, x3),         wp[c * 3 + 2]);
                xs0[c] = x2; xs1[c] = x3;
            }
            float2 f = unpack2(a2);
            S.ht[d * 130 + p] = f.x;
            S.ht[d * 130 + p + 1] = f.y;
        }
    }
    __syncthreads();

    // ---- LN stats partials ----
    {
        int pos = t & 127;
        float s = 0.f, ss = 0.f;
#pragma unroll 4
        for (int dd = half * 64; dd < half * 64 + 64; dd++) {
            float v = S.ht[dd * 130 + pos];
            s += v; ss = fmaf(v, v, ss);
        }
        S.scp[t] = s; S.scp[256 + t] = ss;
    }
    __syncthreads();
    if (t < 128) {
        float s = S.scp[t] + S.scp[128 + t];
        float ss = S.scp[256 + t] + S.scp[384 + t];
        float m = s * (1.f / 128.f);
        float var = ss * (1.f / 128.f) - m * m;
        S.mv[t] = m; S.rv[t] = rsqrtf(var + 1e-5f);
    } else if (t < 160) {
        int j = t - 128;
        float sw = 0.f, sb = 0.f;
#pragma unroll
        for (int seg = 0; seg < 8; seg++) {
            sw += S.redw[seg * 32 + j];
            sb += S.redb[seg * 32 + j];
        }
        S.cw1[j] = sw; S.cb1[j] = sb;
    }
    __syncthreads();

    // ---- scores on RAW h with folded LN affine ----
    {
        const int pp = t & 63;
        const int p0 = 2 * pp;
        const int jq = t >> 6;
        const int j0 = 8 * jq;
        ull acc2[2][4];
#pragma unroll
        for (int r = 0; r < 2; r++)
#pragma unroll
            for (int c = 0; c < 4; c++) acc2[r][c] = 0ull;
        for (int dd = 0; dd < 128; dd++) {
            float2 h2 = *reinterpret_cast<const float2*>(&S.ht[dd * 130 + p0]);
            ull hx = pack2(h2.x, h2.x), hy = pack2(h2.y, h2.y);
            ulonglong2 wpa = *reinterpret_cast<const ulonglong2*>(&S.w1[dd * 32 + j0]);
            ulonglong2 wpb = *reinterpret_cast<const ulonglong2*>(&S.w1[dd * 32 + j0 + 4]);
            fma2(acc2[0][0], hx, wpa.x); fma2(acc2[0][1], hx, wpa.y);
            fma2(acc2[0][2], hx, wpb.x); fma2(acc2[0][3], hx, wpb.y);
            fma2(acc2[1][0], hy, wpa.x); fma2(acc2[1][1], hy, wpa.y);
            fma2(acc2[1][2], hy, wpb.x); fma2(acc2[1][3], hy, wpb.y);
        }
#pragma unroll
        for (int r = 0; r < 2; r++) {
            float rvp = S.rv[p0 + r];
            float rm = rvp * S.mv[p0 + r];
            float sp = 0.f;
#pragma unroll
            for (int c = 0; c < 4; c++) {
                float2 f = unpack2(acc2[r][c]);
                int j = j0 + 2 * c;
                float v0 = rvp * f.x - rm * S.cw1[j]     + S.cb1[j]     + S.b1[j];
                float v1 = rvp * f.y - rm * S.cw1[j + 1] + S.cb1[j + 1] + S.b1[j + 1];
                sp = fmaf(tanh_fast(v0), S.w2[j],     sp);
                sp = fmaf(tanh_fast(v1), S.w2[j + 1], sp);
            }
            S.scp[jq * 128 + p0 + r] = sp;
        }
    }
    __syncthreads();

    // ---- combine + softmax per chunk ----
    if (t < 128) {
        float v = S.scp[t] + S.scp[128 + t] + S.scp[256 + t] + S.scp[384 + t] + ca2_b[0];
        float m = v;
#pragma unroll
        for (int o = 8; o; o >>= 1) m = fmaxf(m, __shfl_xor_sync(0xffffffffu, m, o, 16));
        float e = __expf(v - m);
        float sm = e;
#pragma unroll
        for (int o = 8; o; o >>= 1) sm += __shfl_xor_sync(0xffffffffu, sm, o, 16);
        float wv = e / sm;
        float aval = wv * S.rv[t];
        S.wgt[t] = aval;
        float cc = aval * S.mv[t];
#pragma unroll
        for (int o = 8; o; o >>= 1) cc += __shfl_xor_sync(0xffffffffu, cc, o, 16);
        if ((t & 15) == 0) S.chC[t >> 4] = cc;
    }
    __syncthreads();

    // ---- weighted sums on RAW h with folded LN ----
    {
        float gd = S.lng[d], bd = S.lnb[d];
        for (int c = 4 * half; c < 4 * half + 4; c++) {
            float a = 0.f;
#pragma unroll
            for (int p = 0; p < 16; p++)
                a = fmaf(S.wgt[c * 16 + p], S.ht[d * 130 + c * 16 + p], a);
            float sv = fmaf(gd, a - S.chC[c], bd);
            S.summ[c * 128 + d] = sv;
            g_summ[(b * 128 + g * 8 + c) * 128 + d] = sv;
        }
    }
    __syncthreads();

    // ---- ep projection -> angles, parallelized: 192 threads, 32-dim slices ----
    {
        if (t < 192) {
            int r = t / 24, rem = t % 24;
            int j = rem >> 2, qq = rem & 3;
            float a = (qq == 0) ? S.epb[j] : 0.f;
#pragma unroll 4
            for (int dd = qq * 32; dd < qq * 32 + 32; dd++)
                a = fmaf(S.summ[r * 128 + dd], S.epw[dd * 6 + j], a);
            S.scp[t] = a;
        }
    }
    __syncthreads();
    if (t < 48) {
        int r = t / 6, j = t % 6;
        int base = r * 24 + j * 4;
        float a = S.scp[base] + S.scp[base + 1] + S.scp[base + 2] + S.scp[base + 3];
        g_params[(b * 128 + g * 8 + r) * 128 + 120 + j] =
            tanhf(a) * 3.14159265358979323846f;
    }
}

// ===========================================================================
// Kernel k_pp: pp projection GEMM  (16384 x 128) @ (128 x 120), f32x2 packed
// ===========================================================================
struct KPSmem {
    float w[128 * 128];
    float s[64 * 129];
};

__global__ __launch_bounds__(256) void k_pp(
    const float* __restrict__ pp_w, const float* __restrict__ pp_b)
{
    extern __shared__ char smem_raw[];
    KPSmem& S = *reinterpret_cast<KPSmem*>(smem_raw);
    const int t = threadIdx.x;
    const int r0 = blockIdx.x * 64;

    for (int i = t; i < 128 * 128; i += 256) S.w[i] = 0.f;
    __syncthreads();
    for (int i = t; i < 128 * 120; i += 256) {
        int dd = i / 120, j = i % 120;
        S.w[dd * 128 + j] = pp_w[i];
    }
    for (int i = t; i < 64 * 128; i += 256) {
        int r = i >> 7, c = i & 127;
        S.s[r * 129 + c] = g_summ[(r0 + r) * 128 + c];
    }
    __syncthreads();

    const int tx = t & 15;
    const int ty = t >> 4;
    ull acc2[4][4];
#pragma unroll
    for (int i = 0; i < 4; i++)
#pragma unroll
        for (int c = 0; c < 4; c++) acc2[i][c] = 0ull;

    for (int dd = 0; dd < 128; dd++) {
        ulonglong2 wpa = *reinterpret_cast<const ulonglong2*>(&S.w[dd * 128 + 8 * tx]);
        ulonglong2 wpb = *reinterpret_cast<const ulonglong2*>(&S.w[dd * 128 + 8 * tx + 4]);
        ull sv2[4];
#pragma unroll
        for (int i = 0; i < 4; i++) {
            float sv = S.s[(4 * ty + i) * 129 + dd];
            sv2[i] = pack2(sv, sv);
        }
#pragma unroll
        for (int i = 0; i < 4; i++) {
            fma2(acc2[i][0], sv2[i], wpa.x);
            fma2(acc2[i][1], sv2[i], wpa.y);
            fma2(acc2[i][2], sv2[i], wpb.x);
            fma2(acc2[i][3], sv2[i], wpb.y);
        }
    }
#pragma unroll
    for (int i = 0; i < 4; i++) {
        int gr = r0 + 4 * ty + i;
#pragma unroll
        for (int c = 0; c < 4; c++) {
            float2 f = unpack2(acc2[i][c]);
            int j = 8 * tx + 2 * c;
            if (j < 120)     g_params[gr * 128 + j]     = f.x + pp_b[j];
            if (j + 1 < 120) g_params[gr * 128 + j + 1] = f.y + pp_b[j + 1];
        }
    }
}

// ===========================================================================
// Kernel 2: quantum circuit (warp per row) + op projection + LN + SiLU
//           + fused sequence-attention score
// ===========================================================================
#define TBL_STRIDE 208

__device__ __forceinline__ void apply_su2(int q, float Pr, float Pi, float Qr, float Qi,
    int lane, float& ar0, float& ai0, float& ar1, float& ai1)
{
    if (q == 5) {
        float n0r =  Pr * ar0 - Pi * ai0 + Qr * ar1 - Qi * ai1;
        float n0i =  Pr * ai0 + Pi * ar0 + Qr * ai1 + Qi * ar1;
        float n1r = -Qr * ar0 - Qi * ai0 + Pr * ar1 + Pi * ai1;
        float n1i = -Qr * ai0 + Qi * ar0 + Pr * ai1 - Pi * ar1;
        ar0 = n0r; ai0 = n0i; ar1 = n1r; ai1 = n1i;
    } else {
        int m = 1 << (4 - q);
        float br0 = __shfl_xor_sync(0xffffffffu, ar0, m), bi0 = __shfl_xor_sync(0xffffffffu, ai0, m);
        float br1 = __shfl_xor_sync(0xffffffffu, ar1, m), bi1 = __shfl_xor_sync(0xffffffffu, ai1, m);
        int bit = (lane >> (4 - q)) & 1;
        float lPi = bit ? -Pi : Pi;
        float lQr = bit ? -Qr : Qr;
        float n0r = Pr * ar0 - lPi * ai0 + lQr * br0 - Qi * bi0;
        float n0i = Pr * ai0 + lPi * ar0 + lQr * bi0 + Qi * br0;
        float n1r = Pr * ar1 - lPi * ai1 + lQr * br1 - Qi * bi1;
        float n1i = Pr * ai1 + lPi * ar1 + lQr * bi1 + Qi * br1;
        ar0 = n0r; ai0 = n0i; ar1 = n1r; ai1 = n1i;
    }
}

__device__ __forceinline__ void apply_crx(int cq, int tq, float c, float s,
    int lane, float& ar0, float& ai0, float& ar1, float& ai1)
{
    if (cq == 5) {
        int m = 1 << (4 - tq);
        float br1 = __shfl_xor_sync(0xffffffffu, ar1, m), bi1 = __shfl_xor_sync(0xffffffffu, ai1, m);
        ar1 = c * ar1 + s * bi1; ai1 = c * ai1 - s * br1;
    } else if (tq == 5) {
        if ((lane >> (4 - cq)) & 1) {
            float nr0 = c * ar0 + s * ai1, ni0 = c * ai0 - s * ar1;
            float nr1 = c * ar1 + s * ai0, ni1 = c * ai1 - s * ar0;
            ar0 = nr0; ai0 = ni0; ar1 = nr1; ai1 = ni1;
        }
    } else {
        int m = 1 << (4 - tq);
        float br0 = __shfl_xor_sync(0xffffffffu, ar0, m), bi0 = __shfl_xor_sync(0xffffffffu, ai0, m);
        float br1 = __shfl_xor_sync(0xffffffffu, ar1, m), bi1 = __shfl_xor_sync(0xffffffffu, ai1, m);
        if ((lane >> (4 - cq)) & 1) {
            ar0 = c * ar0 + s * bi0; ai0 = c * ai0 - s * br0;
            ar1 = c * ar1 + s * bi1; ai1 = c * ai1 - s * br1;
        }
    }
}

__global__ __launch_bounds__(256) void k2(
    const float* __restrict__ op_w, const float* __restrict__ op_b,
    const float* __restrict__ ln2_g, const float* __restrict__ ln2_b,
    const float* __restrict__ sa1_w, const float* __restrict__ sa1_b,
    const float* __restrict__ sa2_w, const float* __restrict__ sa2_b)
{
    int tt = threadIdx.x;
    int w = tt >> 5;
    int lane = tt & 31;
    int r = blockIdx.x * 8 + w;

    __shared__ float s_par[8][128];
    __shared__ __align__(16) float s_tbl[8][TBL_STRIDE];
    __shared__ float w1s[128 * 32];
    __shared__ float b1s[32], w2s[32];

    for (int i = tt; i < 4096; i += 256) w1s[i] = sa1_w[i];
    if (tt < 32) { b1s[tt] = sa1_b[tt]; w2s[tt] = sa2_w[tt]; }

#pragma unroll
    for (int j = 0; j < 4; j++)
        s_par[w][lane + 32 * j] = g_params[r * 128 + lane + 32 * j];
    __syncthreads();

    const float* par = s_par[w];
    float* T = s_tbl[w];

    if (lane < 24) {
        int a = lane / 6, i = lane % 6;
        const float* base = par + (a >> 1) * 60 + (a & 1) * 30;
        float sa, ca; __sincosf(0.5f * base[3 * i],     &sa, &ca);
        float sb, cb; __sincosf(0.5f * base[3 * i + 1], &sb, &cb);
        float sg, cg; __sincosf(0.5f * base[3 * i + 2], &sg, &cg);
        float ur = cb * ca, ui = sb * sa;
        float wr = sb * ca, wi = -cb * sa;
        T[4 * lane + 0] = cg * ur + sg * ui;
        T[4 * lane + 1] = cg * ui - sg * ur;
        T[4 * lane + 2] = sg * wi - cg * wr;
        T[4 * lane + 3] = cg * wi + sg * wr;
    }
    for (int gg = lane; gg < 48; gg += 32) {
        int a = gg / 12, j = gg % 12;
        const float* base = par + (a >> 1) * 60 + (a & 1) * 30;
        float s, c; __sincosf(0.5f * base[18 + j], &s, &c);
        T[96 + 2 * gg] = c; T[97 + 2 * gg] = s;
    }
    if (lane < 6) {
        float s, c; __sincosf(0.5f * par[120 + lane], &s, &c);
        T[192 + 2 * lane] = c; T[193 + 2 * lane] = s;
    }
    __syncwarp();

    float ar0, ai0 = 0.f, ar1, ai1 = 0.f;
    {
        float a0 = 1.f, a1 = 1.f;
#pragma unroll
        for (int i = 0; i < 5; i++) {
            float c = T[192 + 2 * i], s = T[193 + 2 * i];
            float f = ((lane >> (4 - i)) & 1) ? s : c;
            a0 *= f; a1 *= f;
        }
        ar0 = a0 * T[202]; ar1 = a1 * T[203];
    }

#pragma unroll
    for (int a = 0; a < 4; a++) {
        const float* F = T + a * 24;
        const float* C = T + 96 + a * 24;
#pragma unroll
        for (int i = 0; i < NQ; i++) {
            float4 pq = *reinterpret_cast<const float4*>(&F[4 * i]);
            apply_su2(i, pq.x, pq.y, pq.z, pq.w, lane, ar0, ai0, ar1, ai1);
        }
#pragma unroll
        for (int j = 0; j < 6; j++) {
            float2 cs = *reinterpret_cast<const float2*>(&C[2 * j]);
            apply_crx(j, (j + 1) % NQ, cs.x, cs.y, lane, ar0, ai0, ar1, ai1);
        }
#pragma unroll
        for (int j = 6; j < 12; j++) {
            float2 cs = *reinterpret_cast<const float2*>(&C[2 * j]);
            int i = 11 - j;
            apply_crx(i, (i + NQ - 1) % NQ, cs.x, cs.y, lane, ar0, ai0, ar1, ai1);
        }
    }

    float qv[18];
#pragma unroll
    for (int i = 0; i < NQ; i++) {
        float cr, ci, z;
        float n0 = ar0 * ar0 + ai0 * ai0;
        float n1 = ar1 * ar1 + ai1 * ai1;
        if (i == 5) {
            cr = ar0 * ar1 + ai0 * ai1;
            ci = ar0 * ai1 - ai0 * ar1;
            z  = n0 - n1;
        } else {
            int m = 1 << (4 - i);
            float br0 = __shfl_xor_sync(0xffffffffu, ar0, m), bi0 = __shfl_xor_sync(0xffffffffu, ai0, m);
            float br1 = __shfl_xor_sync(0xffffffffu, ar1, m), bi1 = __shfl_xor_sync(0xffffffffu, ai1, m);
            if (((lane >> (4 - i)) & 1) == 0) {
                cr = ar0 * br0 + ai0 * bi0 + ar1 * br1 + ai1 * bi1;
                ci = ar0 * bi0 - ai0 * br0 + ar1 * bi1 - ai1 * br1;
                z  = n0 + n1;
            } else {
                cr = 0.f; ci = 0.f; z = -(n0 + n1);
            }
        }
#pragma unroll
        for (int o = 16; o; o >>= 1) {
            cr += __shfl_xor_sync(0xffffffffu, cr, o);
            ci += __shfl_xor_sync(0xffffffffu, ci, o);
            z  += __shfl_xor_sync(0xffffffffu, z, o);
        }
        qv[i] = 2.f * cr; qv[6 + i] = 2.f * ci; qv[12 + i] = z;
    }

    float acc[4];
#pragma unroll
    for (int j = 0; j < 4; j++) {
        int d = lane + 32 * j;
        float a = op_b[d];
#pragma unroll
        for (int k = 0; k < 18; k++) a = fmaf(qv[k], __ldg(&op_w[k * 128 + d]), a);
        acc[j] = a;
    }
    float sum = acc[0] + acc[1] + acc[2] + acc[3];
#pragma unroll
    for (int o = 16; o; o >>= 1) sum += __shfl_xor_sync(0xffffffffu, sum, o);
    float mean = sum * (1.f / 128.f);
    float vs = 0.f;
#pragma unroll
    for (int j = 0; j < 4; j++) { float d0 = acc[j] - mean; vs = fmaf(d0, d0, vs); }
#pragma unroll
    for (int o = 16; o; o >>= 1) vs += __shfl_xor_sync(0xffffffffu, vs, o);
    float rstd = rsqrtf(vs * (1.f / 128.f) + 1e-5f);

    float* cfrow = s_par[w];
#pragma unroll
    for (int j = 0; j < 4; j++) {
        int d = lane + 32 * j;
        float xv = (acc[j] - mean) * rstd * ln2_g[d] + ln2_b[d];
        float cf = xv / (1.f + __expf(-xv));
        g_cf[r * 128 + d] = cf;
        cfrow[d] = cf;
    }
    __syncwarp();

    {
        float a = b1s[lane];
#pragma unroll 4
        for (int dd = 0; dd < 128; dd++)
            a = fmaf(cfrow[dd], w1s[dd * 32 + lane], a);
        float v = tanh_fast(a) * w2s[lane];
#pragma unroll
        for (int o = 16; o; o >>= 1) v += __shfl_xor_sync(0xffffffffu, v, o);
        if (lane == 0) g_ss[r] = v + sa2_b[0];
    }
}

// ===========================================================================
// Kernel k3b1: per-batch softmax (redundant x4) + partial weighted sum
// grid = BATCH*4 (batch, channel-group); 128 threads
// ===========================================================================
__global__ __launch_bounds__(128) void k3b1()
{
    int b = blockIdx.x >> 2, dg = blockIdx.x & 3;
    int t = threadIdx.x, lane = t & 31, w = t >> 5;
    const float* cf = g_cf + (size_t)b * NCHUNK * DM;

    __shared__ float red[8];
    __shared__ float sw_s[NCHUNK];
    __shared__ float part[4][32];

    // softmax over 128 chunks
    float v = g_ss[b * NCHUNK + t];
    float m = v;
#pragma unroll
    for (int o = 16; o; o >>= 1) m = fmaxf(m, __shfl_xor_sync(0xffffffffu, m, o));
    if (lane == 0) red[w] = m;
    __syncthreads();
    float mg = fmaxf(fmaxf(red[0], red[1]), fmaxf(red[2], red[3]));
    float e = __expf(v - mg);
    float sl = e;
#pragma unroll
    for (int o = 16; o; o >>= 1) sl += __shfl_xor_sync(0xffffffffu, sl, o);
    if (lane == 0) red[4 + w] = sl;
    __syncthreads();
    float tot = red[4] + red[5] + red[6] + red[7];
    sw_s[t] = e / tot;
    __syncthreads();

    // partial weighted sum: warp w handles 32 chunks, lane = channel within group
    int ch = dg * 32 + lane;
    float acc = 0.f;
#pragma unroll 8
    for (int n = w * 32; n < w * 32 + 32; n++)
        acc = fmaf(sw_s[n], __ldg(&cf[n * DM + ch]), acc);
    part[w][lane] = acc;
    __syncthreads();
    if (t < 32)
        g_rep[b * DM + dg * 32 + t] = part[0][t] + part[1][t] + part[2][t] + part[3][t];
}

// ===========================================================================
// Kernel k3b2: classifier (one block of 64 per batch)
// ===========================================================================
__global__ __launch_bounds__(64) void k3b2(
    const float* __restrict__ cl1_w, const float* __restrict__ cl1_b,
    const float* __restrict__ cl2_w, const float* __restrict__ cl2_b,
    float* __restrict__ out)
{
    int b = blockIdx.x;
    int t = threadIdx.x;
    __shared__ float rep_s[DM];
    __shared__ float u_s[64];

    rep_s[t] = g_rep[b * DM + t];
    rep_s[t + 64] = g_rep[b * DM + t + 64];
    __syncthreads();

    float a = cl1_b[t];
#pragma unroll 4
    for (int d = 0; d < DM; d++) a = fmaf(rep_s[d], __ldg(&cl1_w[d * 64 + t]), a);
    u_s[t] = a / (1.f + __expf(-a));
    __syncthreads();
    if (t < 2) {
        float o = cl2_b[t];
#pragma unroll 4
        for (int j = 0; j < 64; j++) o = fmaf(u_s[j], __ldg(&cl2_w[j * 2 + t]), o);
        out[b * 2 + t] = o;
    }
}

// ===========================================================================
extern "C" void kernel_launch(void* const* d_in, const int* in_sizes, int n_in,
                              void* d_out, int out_size)
{
    const float* x      = (const float*)d_in[0];
    const float* conv_w = (const float*)d_in[1];
    const float* conv_b = (const float*)d_in[2];
    const float* ln1_g  = (const float*)d_in[3];
    const float* ln1_b  = (const float*)d_in[4];
    const float* ca1_w  = (const float*)d_in[5];
    const float* ca1_b  = (const float*)d_in[6];
    const float* ca2_w  = (const float*)d_in[7];
    const float* ca2_b  = (const float*)d_in[8];
    const float* pp_w   = (const float*)d_in[9];
    const float* pp_b   = (const float*)d_in[10];
    const float* ep_w   = (const float*)d_in[11];
    const float* ep_b   = (const float*)d_in[12];
    const float* op_w   = (const float*)d_in[13];
    const float* op_b   = (const float*)d_in[14];
    const float* ln2_g  = (const float*)d_in[15];
    const float* ln2_b  = (const float*)d_in[16];
    const float* sa1_w  = (const float*)d_in[17];
    const float* sa1_b  = (const float*)d_in[18];
    const float* sa2_w  = (const float*)d_in[19];
    const float* sa2_b  = (const float*)d_in[20];
    const float* cl1_w  = (const float*)d_in[21];
    const float* cl1_b  = (const float*)d_in[22];
    const float* cl2_w  = (const float*)d_in[23];
    const float* cl2_b  = (const float*)d_in[24];
    float* out = (float*)d_out;

    cudaFuncSetAttribute(k1, cudaFuncAttributeMaxDynamicSharedMemorySize, (int)sizeof(K1Smem));
    cudaFuncSetAttribute(k_pp, cudaFuncAttributeMaxDynamicSharedMemorySize, (int)sizeof(KPSmem));

    k1<<<BATCH * 16, 256, sizeof(K1Smem)>>>(x, conv_w, conv_b, ln1_g, ln1_b,
                                            ca1_w, ca1_b, ca2_w, ca2_b, ep_w, ep_b);
    k_pp<<<NROWS / 64, 256, sizeof(KPSmem)>>>(pp_w, pp_b);
    k2<<<NROWS / 8, 256>>>(op_w, op_b, ln2_g, ln2_b, sa1_w, sa1_b, sa2_w, sa2_b);
    k3b1<<<BATCH * 4, 128>>>();
    k3b2<<<BATCH, 64>>>(cl1_w, cl1_b, cl2_w, cl2_b, out);
}